// round 8
// baseline (speedup 1.0000x reference)
#include <cuda_runtime.h>
#include <cuda_bf16.h>
#include <math.h>
#include <stdint.h>

// ---------------- scratch (device globals; no allocations allowed) -----------
__device__ __nv_bfloat16 g_Xh[4096 * 2048],  g_Xl[4096 * 2048];
__device__ __nv_bfloat16 g_Xqh[4096 * 1536], g_Xql[4096 * 1536];
__device__ __nv_bfloat16 g_Cbh[4096 * 512],  g_Cbl[4096 * 512];
__device__ __nv_bfloat16 g_Qh[4096 * 2048],  g_Ql[4096 * 2048];
__device__ __nv_bfloat16 g_Kh[16 * 4096 * 128], g_Kl[16 * 4096 * 128];
__device__ __nv_bfloat16 g_Vth[16 * 128 * 4096], g_Vtl[16 * 128 * 4096];
__device__ __nv_bfloat16 g_AOh[4096 * 2048], g_AOl[4096 * 2048];

__device__ __nv_bfloat16 g_Wqd_hi[1536 * 2048], g_Wqd_lo[1536 * 2048];
__device__ __nv_bfloat16 g_Wqu_hi[2048 * 1536], g_Wqu_lo[2048 * 1536];
__device__ __nv_bfloat16 g_Wkvd_hi[512 * 2048], g_Wkvd_lo[512 * 2048];
__device__ __nv_bfloat16 g_Wo_hi[2048 * 2048], g_Wo_lo[2048 * 2048];
__device__ __nv_bfloat16 g_kupT_hi[16 * 128 * 512], g_kupT_lo[16 * 128 * 512];
__device__ __nv_bfloat16 g_vupT_hi[16 * 128 * 512], g_vupT_lo[16 * 128 * 512];

// ---------------- prep kernels ------------------------------------------------
struct ConvSeg {
    const float* src;
    __nv_bfloat16* hi;
    __nv_bfloat16* lo;
    int n4;
};

__device__ __forceinline__ void split4(const float* src, __nv_bfloat16* hi,
                                       __nv_bfloat16* lo, int i)
{
    float4 v = ((const float4*)src)[i];
    __nv_bfloat16 h0 = __float2bfloat16(v.x), h1 = __float2bfloat16(v.y);
    __nv_bfloat16 h2 = __float2bfloat16(v.z), h3 = __float2bfloat16(v.w);
    __nv_bfloat162 hh[2] = {__halves2bfloat162(h0, h1), __halves2bfloat162(h2, h3)};
    __nv_bfloat162 ll[2] = {
        __halves2bfloat162(__float2bfloat16(v.x - __bfloat162float(h0)),
                           __float2bfloat16(v.y - __bfloat162float(h1))),
        __halves2bfloat162(__float2bfloat16(v.z - __bfloat162float(h2)),
                           __float2bfloat16(v.w - __bfloat162float(h3)))};
    *(uint2*)(hi + i * 4) = *(uint2*)hh;
    *(uint2*)(lo + i * 4) = *(uint2*)ll;
}

__global__ void conv_plain_multi(ConvSeg s0, ConvSeg s1, ConvSeg s2, ConvSeg s3, ConvSeg s4)
{
    const int g = blockIdx.x * blockDim.x + threadIdx.x;
    const int stride = gridDim.x * blockDim.x;
    for (int i = g; i < s0.n4; i += stride) split4(s0.src, s0.hi, s0.lo, i);
    for (int i = g; i < s1.n4; i += stride) split4(s1.src, s1.hi, s1.lo, i);
    for (int i = g; i < s2.n4; i += stride) split4(s2.src, s2.hi, s2.lo, i);
    for (int i = g; i < s3.n4; i += stride) split4(s3.src, s3.hi, s3.lo, i);
    for (int i = g; i < s4.n4; i += stride) split4(s4.src, s4.hi, s4.lo, i);
}

// both kup and vup: [Z][K][N] fp32 -> planes [Z][N][K]
__global__ void conv_transpose2(const float* __restrict__ ka, const float* __restrict__ va,
                                __nv_bfloat16* __restrict__ khi, __nv_bfloat16* __restrict__ klo,
                                __nv_bfloat16* __restrict__ vhi, __nv_bfloat16* __restrict__ vlo,
                                int Z, int K, int N)
{
    long total = (long)Z * K * N;
    long i = (long)blockIdx.x * blockDim.x + threadIdx.x;
    if (i >= 2 * total) return;
    const float* in;
    __nv_bfloat16 *hi, *lo;
    long j = i;
    if (i < total) { in = ka; hi = khi; lo = klo; }
    else { j -= total; in = va; hi = vhi; lo = vlo; }
    int n = (int)(j % N);
    long t = j / N;
    int k = (int)(t % K);
    int z = (int)(t / K);
    float x = in[j];
    __nv_bfloat16 h = __float2bfloat16(x);
    long o = ((long)z * N + n) * K + k;
    hi[o] = h;
    lo[o] = __float2bfloat16(x - __bfloat162float(h));
}

// ---------------- shared helpers ---------------------------------------------
__device__ __forceinline__ uint32_t su(const void* p) {
    return (uint32_t)__cvta_generic_to_shared(p);
}
__device__ __forceinline__ void ldsm4(uint32_t* r, uint32_t addr) {
    asm volatile("ldmatrix.sync.aligned.m8n8.x4.shared.b16 {%0,%1,%2,%3}, [%4];"
                 : "=r"(r[0]), "=r"(r[1]), "=r"(r[2]), "=r"(r[3]) : "r"(addr));
}
__device__ __forceinline__ void mma16816(float* c, const uint32_t* a, const uint32_t* b) {
    asm volatile("mma.sync.aligned.m16n8k16.row.col.f32.bf16.bf16.f32 "
                 "{%0,%1,%2,%3}, {%4,%5,%6,%7}, {%8,%9}, {%0,%1,%2,%3};"
                 : "+f"(c[0]), "+f"(c[1]), "+f"(c[2]), "+f"(c[3])
                 : "r"(a[0]), "r"(a[1]), "r"(a[2]), "r"(a[3]), "r"(b[0]), "r"(b[1]));
}
__device__ __forceinline__ void cpa16(uint32_t dst, const void* src) {
    asm volatile("cp.async.cg.shared.global [%0], [%1], 16;" :: "r"(dst), "l"(src));
}
__device__ __forceinline__ uint32_t pack2(__nv_bfloat16 a, __nv_bfloat16 b) {
    __nv_bfloat162 t = __halves2bfloat162(a, b);
    return *(uint32_t*)&t;
}

// ---------------- bf16x3 mma.sync GEMM (all-plane, NS=2, 2 CTAs/SM) -----------
#define BM 128
#define BN 128
#define BK 32
#define LDSS 40
#define PLANE_ELE (128 * LDSS)
#define PLANE_BYTES (PLANE_ELE * 2)
#define STAGE_BYTES (4 * PLANE_BYTES)
#define NS 2
#define GEMM_SMEM (NS * STAGE_BYTES)     // 81920 -> 2 CTAs/SM

// EPI: 0 = fp32 C; 1 = bf16 hi/lo planes row-major (with merged-N support)
template <int EPI>
__global__ __launch_bounds__(256, 2)
void gemm_tc(const __nv_bfloat16* __restrict__ Ahi, const __nv_bfloat16* __restrict__ Alo,
             const __nv_bfloat16* __restrict__ Bhi, const __nv_bfloat16* __restrict__ Blo,
             float* __restrict__ C,
             __nv_bfloat16* __restrict__ Ohi, __nv_bfloat16* __restrict__ Olo,
             int M, int N, int K, int lda, int ldc,
             const __nv_bfloat16* __restrict__ B2hi, const __nv_bfloat16* __restrict__ B2lo,
             __nv_bfloat16* __restrict__ O2hi, __nv_bfloat16* __restrict__ O2lo,
             int nSplit, int ldc2)
{
    extern __shared__ __nv_bfloat16 smem[];

    const int tid = threadIdx.x;
    const int mBase = blockIdx.y * BM;
    int nBase = blockIdx.x * BN;

    const __nv_bfloat16 *BhiL, *BloL;
    __nv_bfloat16 *OhiL, *OloL;
    int ldcL = ldc;
    if (EPI == 1 && nBase >= nSplit) {
        BhiL = B2hi; BloL = B2lo; OhiL = O2hi; OloL = O2lo;
        nBase -= nSplit; ldcL = ldc2;
    } else {
        BhiL = Bhi; BloL = Blo; OhiL = Ohi; OloL = Olo;
    }

    const int ldRow = tid >> 1;
    const int ldCol = (tid & 1) * 16;
    const uint32_t stsB = (uint32_t)(ldRow * LDSS + ldCol) * 2;

    const int lane = tid & 31;
    const int wid = tid >> 5;
    const int wm = wid >> 2;
    const int wn = wid & 3;
    const int aRowL = wm * 64 + (lane & 15);
    const int aKL = ((lane >> 4) << 3);
    const int bRowL = wn * 32 + ((lane >> 4) << 3) + (lane & 7);
    const int bKL = ((lane >> 3) & 1) << 3;

    const uint32_t smemBase = su(smem);
    const int nt = K / BK;

    const __nv_bfloat16* pAh = Ahi + (long)(mBase + ldRow) * lda + ldCol;
    const __nv_bfloat16* pAl = Alo + (long)(mBase + ldRow) * lda + ldCol;
    const __nv_bfloat16* pBh = BhiL + (long)(nBase + ldRow) * K + ldCol;
    const __nv_bfloat16* pBl = BloL + (long)(nBase + ldRow) * K + ldCol;

    auto loadStage = [&](int s, int kt) {
        const uint32_t d = smemBase + s * STAGE_BYTES + stsB;
        const long off = (long)kt * BK;
        cpa16(d, pAh + off); cpa16(d + 16, pAh + off + 8);
        cpa16(d + PLANE_BYTES, pAl + off); cpa16(d + PLANE_BYTES + 16, pAl + off + 8);
        cpa16(d + 2 * PLANE_BYTES, pBh + off); cpa16(d + 2 * PLANE_BYTES + 16, pBh + off + 8);
        cpa16(d + 3 * PLANE_BYTES, pBl + off); cpa16(d + 3 * PLANE_BYTES + 16, pBl + off + 8);
    };

    float acc[4][4][4];
#pragma unroll
    for (int i = 0; i < 4; i++)
#pragma unroll
        for (int j = 0; j < 4; j++)
#pragma unroll
            for (int k = 0; k < 4; k++) acc[i][j][k] = 0.f;

    loadStage(0, 0);
    asm volatile("cp.async.commit_group;" ::: "memory");

    for (int kt = 0; kt < nt; kt++) {
        asm volatile("cp.async.wait_group 0;" ::: "memory");
        __syncthreads();

        if (kt + 1 < nt) {
            loadStage((kt + 1) & 1, kt + 1);
            asm volatile("cp.async.commit_group;" ::: "memory");
        }

        const uint32_t sAh = smemBase + (kt & 1) * STAGE_BYTES;
        const uint32_t sAl = sAh + PLANE_BYTES;
        const uint32_t sBh = sAh + 2 * PLANE_BYTES;
        const uint32_t sBl = sAh + 3 * PLANE_BYTES;

#pragma unroll
        for (int ks = 0; ks < BK; ks += 16) {
            uint32_t Ah[4][4], Al[4][4];
#pragma unroll
            for (int mb = 0; mb < 4; mb++) {
                const uint32_t off = ((aRowL + mb * 16) * LDSS + aKL + ks) * 2;
                ldsm4(Ah[mb], sAh + off);
                ldsm4(Al[mb], sAl + off);
            }
            uint32_t Bh[4][2], Bl[4][2];
#pragma unroll
            for (int nb2 = 0; nb2 < 2; nb2++) {
                const uint32_t off = ((bRowL + nb2 * 16) * LDSS + bKL + ks) * 2;
                uint32_t rg[4];
                ldsm4(rg, sBh + off);
                Bh[nb2 * 2][0] = rg[0]; Bh[nb2 * 2][1] = rg[1];
                Bh[nb2 * 2 + 1][0] = rg[2]; Bh[nb2 * 2 + 1][1] = rg[3];
                ldsm4(rg, sBl + off);
                Bl[nb2 * 2][0] = rg[0]; Bl[nb2 * 2][1] = rg[1];
                Bl[nb2 * 2 + 1][0] = rg[2]; Bl[nb2 * 2 + 1][1] = rg[3];
            }
#pragma unroll
            for (int mb = 0; mb < 4; mb++)
#pragma unroll
                for (int nb = 0; nb < 4; nb++) {
                    mma16816(acc[mb][nb], Ah[mb], Bh[nb]);
                    mma16816(acc[mb][nb], Ah[mb], Bl[nb]);
                    mma16816(acc[mb][nb], Al[mb], Bh[nb]);
                }
        }
        __syncthreads();
    }

#pragma unroll
    for (int mb = 0; mb < 4; mb++) {
        const int r = mBase + wm * 64 + mb * 16 + (lane >> 2);
#pragma unroll
        for (int nb = 0; nb < 4; nb++) {
            const int cc = nBase + wn * 32 + nb * 8 + (lane & 3) * 2;
            float v0 = acc[mb][nb][0], v1 = acc[mb][nb][1];
            float v2 = acc[mb][nb][2], v3 = acc[mb][nb][3];
            if (EPI == 0) {
                *(float2*)&C[(long)r * ldcL + cc] = make_float2(v0, v1);
                *(float2*)&C[(long)(r + 8) * ldcL + cc] = make_float2(v2, v3);
            } else {
                __nv_bfloat16 h0 = __float2bfloat16(v0), h1 = __float2bfloat16(v1);
                __nv_bfloat16 h2 = __float2bfloat16(v2), h3 = __float2bfloat16(v3);
                __nv_bfloat16 l0 = __float2bfloat16(v0 - __bfloat162float(h0));
                __nv_bfloat16 l1 = __float2bfloat16(v1 - __bfloat162float(h1));
                __nv_bfloat16 l2 = __float2bfloat16(v2 - __bfloat162float(h2));
                __nv_bfloat16 l3 = __float2bfloat16(v3 - __bfloat162float(h3));
                *(__nv_bfloat162*)&OhiL[(long)r * ldcL + cc] = __halves2bfloat162(h0, h1);
                *(__nv_bfloat162*)&OhiL[(long)(r + 8) * ldcL + cc] = __halves2bfloat162(h2, h3);
                *(__nv_bfloat162*)&OloL[(long)r * ldcL + cc] = __halves2bfloat162(l0, l1);
                *(__nv_bfloat162*)&OloL[(long)(r + 8) * ldcL + cc] = __halves2bfloat162(l2, l3);
            }
        }
    }
}

// ---------------- fused Q-up + K-up + V-up GEMM (1D grid, role decode) --------
// bid <  512 : Q = Xq @ Wqu^T tile (row-major plane epilogue)
// bid < 1024 : K[h] = C @ kupT[h]^T (row-major plane epilogue)
// bid < 1536 : V[h] = C @ vupT[h]^T (TRANSPOSED plane epilogue [d][row])
__global__ __launch_bounds__(256, 2)
void gemm_qkv(const __nv_bfloat16* __restrict__ xqH, const __nv_bfloat16* __restrict__ xqL,
              const __nv_bfloat16* __restrict__ wquH, const __nv_bfloat16* __restrict__ wquL,
              __nv_bfloat16* __restrict__ qH, __nv_bfloat16* __restrict__ qL,
              const __nv_bfloat16* __restrict__ cbH, const __nv_bfloat16* __restrict__ cbL,
              const __nv_bfloat16* __restrict__ kuH, const __nv_bfloat16* __restrict__ kuL,
              __nv_bfloat16* __restrict__ kH, __nv_bfloat16* __restrict__ kL,
              const __nv_bfloat16* __restrict__ vuH, const __nv_bfloat16* __restrict__ vuL,
              __nv_bfloat16* __restrict__ vtH, __nv_bfloat16* __restrict__ vtL)
{
    extern __shared__ __nv_bfloat16 smem[];
    const int tid = threadIdx.x;
    const int bid = blockIdx.x;

    const __nv_bfloat16 *Ahi, *Alo, *Bhi, *Blo;
    __nv_bfloat16 *Ohi, *Olo;
    int mBase, Kd, lda, ldc, outCol;
    bool transEpi;

    if (bid < 512) {
        mBase = (bid >> 4) * 128;
        outCol = (bid & 15) * 128;
        Ahi = xqH; Alo = xqL; lda = 1536; Kd = 1536;
        Bhi = wquH + (long)outCol * 1536;
        Blo = wquL + (long)outCol * 1536;
        Ohi = qH; Olo = qL; ldc = 2048;
        transEpi = false;
    } else if (bid < 1024) {
        const int t = bid - 512;
        const int h = t >> 5;
        mBase = (t & 31) * 128;
        outCol = 0;
        Ahi = cbH; Alo = cbL; lda = 512; Kd = 512;
        Bhi = kuH + (long)h * 128 * 512;
        Blo = kuL + (long)h * 128 * 512;
        Ohi = kH + (long)h * 4096 * 128;
        Olo = kL + (long)h * 4096 * 128;
        ldc = 128;
        transEpi = false;
    } else {
        const int t = bid - 1024;
        const int h = t >> 5;
        mBase = (t & 31) * 128;
        outCol = 0;
        Ahi = cbH; Alo = cbL; lda = 512; Kd = 512;
        Bhi = vuH + (long)h * 128 * 512;
        Blo = vuL + (long)h * 128 * 512;
        Ohi = vtH + (long)h * 128 * 4096;
        Olo = vtL + (long)h * 128 * 4096;
        ldc = 4096;
        transEpi = true;
    }

    const int ldRow = tid >> 1;
    const int ldCol = (tid & 1) * 16;
    const uint32_t stsB = (uint32_t)(ldRow * LDSS + ldCol) * 2;

    const int lane = tid & 31;
    const int wid = tid >> 5;
    const int wm = wid >> 2;
    const int wn = wid & 3;
    const int aRowL = wm * 64 + (lane & 15);
    const int aKL = ((lane >> 4) << 3);
    const int bRowL = wn * 32 + ((lane >> 4) << 3) + (lane & 7);
    const int bKL = ((lane >> 3) & 1) << 3;

    const uint32_t smemBase = su(smem);
    const int nt = Kd / BK;

    const __nv_bfloat16* pAh = Ahi + (long)(mBase + ldRow) * lda + ldCol;
    const __nv_bfloat16* pAl = Alo + (long)(mBase + ldRow) * lda + ldCol;
    const __nv_bfloat16* pBh = Bhi + (long)ldRow * Kd + ldCol;
    const __nv_bfloat16* pBl = Blo + (long)ldRow * Kd + ldCol;

    auto loadStage = [&](int s, int kt) {
        const uint32_t d = smemBase + s * STAGE_BYTES + stsB;
        const long off = (long)kt * BK;
        cpa16(d, pAh + off); cpa16(d + 16, pAh + off + 8);
        cpa16(d + PLANE_BYTES, pAl + off); cpa16(d + PLANE_BYTES + 16, pAl + off + 8);
        cpa16(d + 2 * PLANE_BYTES, pBh + off); cpa16(d + 2 * PLANE_BYTES + 16, pBh + off + 8);
        cpa16(d + 3 * PLANE_BYTES, pBl + off); cpa16(d + 3 * PLANE_BYTES + 16, pBl + off + 8);
    };

    float acc[4][4][4];
#pragma unroll
    for (int i = 0; i < 4; i++)
#pragma unroll
        for (int j = 0; j < 4; j++)
#pragma unroll
            for (int k = 0; k < 4; k++) acc[i][j][k] = 0.f;

    loadStage(0, 0);
    asm volatile("cp.async.commit_group;" ::: "memory");

    for (int kt = 0; kt < nt; kt++) {
        asm volatile("cp.async.wait_group 0;" ::: "memory");
        __syncthreads();

        if (kt + 1 < nt) {
            loadStage((kt + 1) & 1, kt + 1);
            asm volatile("cp.async.commit_group;" ::: "memory");
        }

        const uint32_t sAh = smemBase + (kt & 1) * STAGE_BYTES;
        const uint32_t sAl = sAh + PLANE_BYTES;
        const uint32_t sBh = sAh + 2 * PLANE_BYTES;
        const uint32_t sBl = sAh + 3 * PLANE_BYTES;

#pragma unroll
        for (int ks = 0; ks < BK; ks += 16) {
            uint32_t Ah[4][4], Al[4][4];
#pragma unroll
            for (int mb = 0; mb < 4; mb++) {
                const uint32_t off = ((aRowL + mb * 16) * LDSS + aKL + ks) * 2;
                ldsm4(Ah[mb], sAh + off);
                ldsm4(Al[mb], sAl + off);
            }
            uint32_t Bh[4][2], Bl[4][2];
#pragma unroll
            for (int nb2 = 0; nb2 < 2; nb2++) {
                const uint32_t off = ((bRowL + nb2 * 16) * LDSS + bKL + ks) * 2;
                uint32_t rg[4];
                ldsm4(rg, sBh + off);
                Bh[nb2 * 2][0] = rg[0]; Bh[nb2 * 2][1] = rg[1];
                Bh[nb2 * 2 + 1][0] = rg[2]; Bh[nb2 * 2 + 1][1] = rg[3];
                ldsm4(rg, sBl + off);
                Bl[nb2 * 2][0] = rg[0]; Bl[nb2 * 2][1] = rg[1];
                Bl[nb2 * 2 + 1][0] = rg[2]; Bl[nb2 * 2 + 1][1] = rg[3];
            }
#pragma unroll
            for (int mb = 0; mb < 4; mb++)
#pragma unroll
                for (int nb = 0; nb < 4; nb++) {
                    mma16816(acc[mb][nb], Ah[mb], Bh[nb]);
                    mma16816(acc[mb][nb], Ah[mb], Bl[nb]);
                    mma16816(acc[mb][nb], Al[mb], Bh[nb]);
                }
        }
        __syncthreads();
    }

#pragma unroll
    for (int mb = 0; mb < 4; mb++) {
        const int r = mBase + wm * 64 + mb * 16 + (lane >> 2);
#pragma unroll
        for (int nb = 0; nb < 4; nb++) {
            const int cc = wn * 32 + nb * 8 + (lane & 3) * 2;
            float v0 = acc[mb][nb][0], v1 = acc[mb][nb][1];
            float v2 = acc[mb][nb][2], v3 = acc[mb][nb][3];
            __nv_bfloat16 h0 = __float2bfloat16(v0), h1 = __float2bfloat16(v1);
            __nv_bfloat16 h2 = __float2bfloat16(v2), h3 = __float2bfloat16(v3);
            __nv_bfloat16 l0 = __float2bfloat16(v0 - __bfloat162float(h0));
            __nv_bfloat16 l1 = __float2bfloat16(v1 - __bfloat162float(h1));
            __nv_bfloat16 l2 = __float2bfloat16(v2 - __bfloat162float(h2));
            __nv_bfloat16 l3 = __float2bfloat16(v3 - __bfloat162float(h3));
            if (!transEpi) {
                const int c = outCol + cc;
                *(__nv_bfloat162*)&Ohi[(long)r * ldc + c] = __halves2bfloat162(h0, h1);
                *(__nv_bfloat162*)&Ohi[(long)(r + 8) * ldc + c] = __halves2bfloat162(h2, h3);
                *(__nv_bfloat162*)&Olo[(long)r * ldc + c] = __halves2bfloat162(l0, l1);
                *(__nv_bfloat162*)&Olo[(long)(r + 8) * ldc + c] = __halves2bfloat162(l2, l3);
            } else {
                Ohi[(long)cc * ldc + r] = h0;
                Ohi[(long)(cc + 1) * ldc + r] = h1;
                Ohi[(long)cc * ldc + r + 8] = h2;
                Ohi[(long)(cc + 1) * ldc + r + 8] = h3;
                Olo[(long)cc * ldc + r] = l0;
                Olo[(long)(cc + 1) * ldc + r] = l1;
                Olo[(long)cc * ldc + r + 8] = l2;
                Olo[(long)(cc + 1) * ldc + r + 8] = l3;
            }
        }
    }
}

// ---------------- tensor-core flash attention --------------------------------
#define FQ_S 136
#define FV_S 72
#define FQH_O 0
#define FQL_O 17408
#define FK_O 34816
#define FV_O 69632
#define FLASH_SMEM (106496 * 2)
#define SCALE_F 0.08838834764831845f

__global__ __launch_bounds__(256)
void flash_tc(const __nv_bfloat16* __restrict__ Qh, const __nv_bfloat16* __restrict__ Ql,
              const __nv_bfloat16* __restrict__ Kh, const __nv_bfloat16* __restrict__ Kl,
              const __nv_bfloat16* __restrict__ Vth, const __nv_bfloat16* __restrict__ Vtl,
              __nv_bfloat16* __restrict__ AOh, __nv_bfloat16* __restrict__ AOl)
{
    extern __shared__ __nv_bfloat16 fsm[];
    // LPT: heavy q-tiles (large qt -> more kv iterations) scheduled first
    const int qt = (int)gridDim.x - 1 - (int)blockIdx.x;
    const int h = blockIdx.y, b = blockIdx.z;
    const int tid = threadIdx.x, lane = tid & 31, w = tid >> 5;
    const float slope = exp2f(-0.5f * (float)(h + 1));
    const int nt = 2 * qt + 2;

    const uint32_t fb = su(fsm);

    {
        const int r = tid >> 1, cb = (tid & 1) * 64;
        const __nv_bfloat16* sh = Qh + (long)(b * 2048 + qt * 128 + r) * 2048 + h * 128 + cb;
        const __nv_bfloat16* sl = Ql + (long)(b * 2048 + qt * 128 + r) * 2048 + h * 128 + cb;
        const uint32_t dh = fb + (FQH_O + r * FQ_S + cb) * 2;
        const uint32_t dl = fb + (FQL_O + r * FQ_S + cb) * 2;
#pragma unroll
        for (int u = 0; u < 8; u++) { cpa16(dh + u * 16, sh + u * 8); cpa16(dl + u * 16, sl + u * 8); }
    }
    auto loadKV = [&](int stg, int jt) {
        const int kr = tid >> 2, kcb = (tid & 3) * 32;
        const long krow = (long)h * 4096 + b * 2048 + jt * 64 + kr;
        const __nv_bfloat16* skh = Kh + krow * 128 + kcb;
        const __nv_bfloat16* skl = Kl + krow * 128 + kcb;
        const uint32_t kdh = fb + (FK_O + stg * 17408 + kr * FQ_S + kcb) * 2;
        const uint32_t kdl = kdh + 8704 * 2;
#pragma unroll
        for (int u = 0; u < 4; u++) { cpa16(kdh + u * 16, skh + u * 8); cpa16(kdl + u * 16, skl + u * 8); }
        const int vr = tid >> 1, vcb = (tid & 1) * 32;
        const long vrow = (long)h * 128 + vr;
        const __nv_bfloat16* svh = Vth + vrow * 4096 + b * 2048 + jt * 64 + vcb;
        const __nv_bfloat16* svl = Vtl + vrow * 4096 + b * 2048 + jt * 64 + vcb;
        const uint32_t vdh = fb + (FV_O + stg * 18432 + vr * FV_S + vcb) * 2;
        const uint32_t vdl = vdh + 9216 * 2;
#pragma unroll
        for (int u = 0; u < 4; u++) { cpa16(vdh + u * 16, svh + u * 8); cpa16(vdl + u * 16, svl + u * 8); }
    };
    loadKV(0, 0);
    asm volatile("cp.async.commit_group;");

    const int aRow = w * 16 + (lane & 15);
    const int aCol8 = (lane >> 4) << 3;
    const int bRow8 = ((lane >> 4) << 3) + (lane & 7);
    const int bCol8 = ((lane >> 3) & 1) << 3;

    float m0 = -1e30f, m1 = -1e30f, l0 = 0.f, l1 = 0.f;
    float o[16][4];
#pragma unroll
    for (int i = 0; i < 16; i++)
#pragma unroll
        for (int j = 0; j < 4; j++) o[i][j] = 0.f;

    const int grow0 = qt * 128 + w * 16 + (lane >> 2);

    for (int jt = 0; jt < nt; jt++) {
        const int cur = jt & 1;
        if (jt > 0) __syncthreads();
        if (jt + 1 < nt) {
            loadKV(cur ^ 1, jt + 1);
            asm volatile("cp.async.commit_group;");
            asm volatile("cp.async.wait_group 1;");
        } else {
            asm volatile("cp.async.wait_group 0;");
        }
        __syncthreads();

        const uint32_t bKH = fb + (FK_O + cur * 17408) * 2;
        const uint32_t bKL = bKH + 8704 * 2;
        const uint32_t bVH = fb + (FV_O + cur * 18432) * 2;
        const uint32_t bVL = bVH + 9216 * 2;

        float s[8][4];
#pragma unroll
        for (int i = 0; i < 8; i++)
#pragma unroll
            for (int j = 0; j < 4; j++) s[i][j] = 0.f;

#pragma unroll
        for (int ks = 0; ks < 8; ks++) {
            uint32_t qh[4], ql[4];
            const uint32_t aoff = (uint32_t)(aRow * FQ_S + ks * 16 + aCol8) * 2;
            ldsm4(qh, fb + FQH_O * 2 + aoff);
            ldsm4(ql, fb + FQL_O * 2 + aoff);
#pragma unroll
            for (int nb2 = 0; nb2 < 4; nb2++) {
                const uint32_t boff = (uint32_t)((nb2 * 16 + bRow8) * FQ_S + ks * 16 + bCol8) * 2;
                uint32_t kh[4], kl[4];
                ldsm4(kh, bKH + boff);
                ldsm4(kl, bKL + boff);
                mma16816(s[2 * nb2],     qh, &kh[0]);
                mma16816(s[2 * nb2],     qh, &kl[0]);
                mma16816(s[2 * nb2],     ql, &kh[0]);
                mma16816(s[2 * nb2 + 1], qh, &kh[2]);
                mma16816(s[2 * nb2 + 1], qh, &kl[2]);
                mma16816(s[2 * nb2 + 1], ql, &kh[2]);
            }
        }

#pragma unroll
        for (int nb = 0; nb < 8; nb++) {
#pragma unroll
            for (int j = 0; j < 2; j++) {
                const int gc = jt * 64 + nb * 8 + (lane & 3) * 2 + j;
                float v = s[nb][j];
                s[nb][j] = (gc > grow0) ? -1e30f
                          : v * SCALE_F - slope * (float)(grow0 - gc);
                float v2 = s[nb][2 + j];
                s[nb][2 + j] = (gc > grow0 + 8) ? -1e30f
                          : v2 * SCALE_F - slope * (float)(grow0 + 8 - gc);
            }
        }

        float mx0 = -1e30f, mx1 = -1e30f;
#pragma unroll
        for (int nb = 0; nb < 8; nb++) {
            mx0 = fmaxf(mx0, fmaxf(s[nb][0], s[nb][1]));
            mx1 = fmaxf(mx1, fmaxf(s[nb][2], s[nb][3]));
        }
        mx0 = fmaxf(mx0, __shfl_xor_sync(0xffffffffu, mx0, 1));
        mx0 = fmaxf(mx0, __shfl_xor_sync(0xffffffffu, mx0, 2));
        mx1 = fmaxf(mx1, __shfl_xor_sync(0xffffffffu, mx1, 1));
        mx1 = fmaxf(mx1, __shfl_xor_sync(0xffffffffu, mx1, 2));
        const float mn0 = fmaxf(m0, mx0), mn1 = fmaxf(m1, mx1);
        const float al0 = __expf(m0 - mn0), al1 = __expf(m1 - mn1);
        m0 = mn0; m1 = mn1;

        float sum0 = 0.f, sum1 = 0.f;
#pragma unroll
        for (int nb = 0; nb < 8; nb++) {
            s[nb][0] = __expf(s[nb][0] - mn0); sum0 += s[nb][0];
            s[nb][1] = __expf(s[nb][1] - mn0); sum0 += s[nb][1];
            s[nb][2] = __expf(s[nb][2] - mn1); sum1 += s[nb][2];
            s[nb][3] = __expf(s[nb][3] - mn1); sum1 += s[nb][3];
        }
        sum0 += __shfl_xor_sync(0xffffffffu, sum0, 1);
        sum0 += __shfl_xor_sync(0xffffffffu, sum0, 2);
        sum1 += __shfl_xor_sync(0xffffffffu, sum1, 1);
        sum1 += __shfl_xor_sync(0xffffffffu, sum1, 2);
        l0 = l0 * al0 + sum0;
        l1 = l1 * al1 + sum1;

#pragma unroll
        for (int nb = 0; nb < 16; nb++) {
            o[nb][0] *= al0; o[nb][1] *= al0;
            o[nb][2] *= al1; o[nb][3] *= al1;
        }

        uint32_t ph[4][4], pl[4][4];
#pragma unroll
        for (int kb = 0; kb < 4; kb++) {
#pragma unroll
            for (int q = 0; q < 4; q++) {
                const float x = s[2 * kb + (q >> 1)][(q & 1) * 2 + 0];
                const float y = s[2 * kb + (q >> 1)][(q & 1) * 2 + 1];
                const __nv_bfloat16 hx = __float2bfloat16(x), hy = __float2bfloat16(y);
                ph[kb][q] = pack2(hx, hy);
                pl[kb][q] = pack2(__float2bfloat16(x - __bfloat162float(hx)),
                                  __float2bfloat16(y - __bfloat162float(hy)));
            }
        }

#pragma unroll
        for (int kb = 0; kb < 4; kb++) {
#pragma unroll
            for (int nb2 = 0; nb2 < 8; nb2++) {
                const uint32_t voff = (uint32_t)((nb2 * 16 + bRow8) * FV_S + kb * 16 + bCol8) * 2;
                uint32_t vh[4], vl[4];
                ldsm4(vh, bVH + voff);
                ldsm4(vl, bVL + voff);
                mma16816(o[2 * nb2],     ph[kb], &vh[0]);
                mma16816(o[2 * nb2],     ph[kb], &vl[0]);
                mma16816(o[2 * nb2],     pl[kb], &vh[0]);
                mma16816(o[2 * nb2 + 1], ph[kb], &vh[2]);
                mma16816(o[2 * nb2 + 1], ph[kb], &vl[2]);
                mma16816(o[2 * nb2 + 1], pl[kb], &vh[2]);
            }
        }
    }

    const float inv0 = 1.f / l0, inv1 = 1.f / l1;
    const long row0 = (long)b * 2048 + qt * 128 + w * 16 + (lane >> 2);
#pragma unroll
    for (int nb = 0; nb < 16; nb++) {
        const int c = h * 128 + nb * 8 + (lane & 3) * 2;
        float x0 = o[nb][0] * inv0, x1 = o[nb][1] * inv0;
        float x2 = o[nb][2] * inv1, x3 = o[nb][3] * inv1;
        __nv_bfloat16 h0 = __float2bfloat16(x0), h1 = __float2bfloat16(x1);
        __nv_bfloat16 h2 = __float2bfloat16(x2), h3 = __float2bfloat16(x3);
        *(__nv_bfloat162*)&AOh[row0 * 2048 + c] = __halves2bfloat162(h0, h1);
        *(__nv_bfloat162*)&AOh[(row0 + 8) * 2048 + c] = __halves2bfloat162(h2, h3);
        *(__nv_bfloat162*)&AOl[row0 * 2048 + c] =
            __halves2bfloat162(__float2bfloat16(x0 - __bfloat162float(h0)),
                               __float2bfloat16(x1 - __bfloat162float(h1)));
        *(__nv_bfloat162*)&AOl[(row0 + 8) * 2048 + c] =
            __halves2bfloat162(__float2bfloat16(x2 - __bfloat162float(h2)),
                               __float2bfloat16(x3 - __bfloat162float(h3)));
    }
}

// ---------------- launch ------------------------------------------------------
extern "C" void kernel_launch(void* const* d_in, const int* in_sizes, int n_in,
                              void* d_out, int out_size)
{
    const float* X    = (const float*)d_in[0];
    const float* Wqd  = (const float*)d_in[1];
    const float* Wqu  = (const float*)d_in[2];
    const float* Wkvd = (const float*)d_in[3];
    const float* kup  = (const float*)d_in[4];
    const float* vup  = (const float*)d_in[5];
    const float* Wo   = (const float*)d_in[6];
    float* out = (float*)d_out;

    __nv_bfloat16 *xH, *xL, *xqH, *xqL, *cbH, *cbL, *qH, *qL, *kH, *kL, *vtH, *vtL, *aoH, *aoL;
    cudaGetSymbolAddress((void**)&xH, g_Xh);   cudaGetSymbolAddress((void**)&xL, g_Xl);
    cudaGetSymbolAddress((void**)&xqH, g_Xqh); cudaGetSymbolAddress((void**)&xqL, g_Xql);
    cudaGetSymbolAddress((void**)&cbH, g_Cbh); cudaGetSymbolAddress((void**)&cbL, g_Cbl);
    cudaGetSymbolAddress((void**)&qH, g_Qh);   cudaGetSymbolAddress((void**)&qL, g_Ql);
    cudaGetSymbolAddress((void**)&kH, g_Kh);   cudaGetSymbolAddress((void**)&kL, g_Kl);
    cudaGetSymbolAddress((void**)&vtH, g_Vth); cudaGetSymbolAddress((void**)&vtL, g_Vtl);
    cudaGetSymbolAddress((void**)&aoH, g_AOh); cudaGetSymbolAddress((void**)&aoL, g_AOl);

    __nv_bfloat16 *wqdH, *wqdL, *wquH, *wquL, *wkvH, *wkvL, *woH, *woL;
    __nv_bfloat16 *kuH, *kuL, *vuH, *vuL;
    cudaGetSymbolAddress((void**)&wqdH, g_Wqd_hi); cudaGetSymbolAddress((void**)&wqdL, g_Wqd_lo);
    cudaGetSymbolAddress((void**)&wquH, g_Wqu_hi); cudaGetSymbolAddress((void**)&wquL, g_Wqu_lo);
    cudaGetSymbolAddress((void**)&wkvH, g_Wkvd_hi); cudaGetSymbolAddress((void**)&wkvL, g_Wkvd_lo);
    cudaGetSymbolAddress((void**)&woH, g_Wo_hi); cudaGetSymbolAddress((void**)&woL, g_Wo_lo);
    cudaGetSymbolAddress((void**)&kuH, g_kupT_hi); cudaGetSymbolAddress((void**)&kuL, g_kupT_lo);
    cudaGetSymbolAddress((void**)&vuH, g_vupT_hi); cudaGetSymbolAddress((void**)&vuL, g_vupT_lo);

    cudaFuncSetAttribute(gemm_tc<0>, cudaFuncAttributeMaxDynamicSharedMemorySize, GEMM_SMEM);
    cudaFuncSetAttribute(gemm_tc<1>, cudaFuncAttributeMaxDynamicSharedMemorySize, GEMM_SMEM);
    cudaFuncSetAttribute(gemm_qkv, cudaFuncAttributeMaxDynamicSharedMemorySize, GEMM_SMEM);
    cudaFuncSetAttribute(flash_tc, cudaFuncAttributeMaxDynamicSharedMemorySize, FLASH_SMEM);

    // ---- prep: 2 launches ----
    ConvSeg s0 = {X,    xH,   xL,   4096 * 2048 / 4};
    ConvSeg s1 = {Wqd,  wqdH, wqdL, 1536 * 2048 / 4};
    ConvSeg s2 = {Wqu,  wquH, wquL, 2048 * 1536 / 4};
    ConvSeg s3 = {Wkvd, wkvH, wkvL, 512 * 2048 / 4};
    ConvSeg s4 = {Wo,   woH,  woL,  2048 * 2048 / 4};
    conv_plain_multi<<<2048, 256>>>(s0, s1, s2, s3, s4);
    conv_transpose2<<<(2 * 16 * 512 * 128 + 255) / 256, 256>>>(
        kup, vup, kuH, kuL, vuH, vuL, 16, 512, 128);

    // 1) [Xq | C] = X @ [Wqd | Wkvd]^T  (merged-N)
    gemm_tc<1><<<dim3(16, 32), 256, GEMM_SMEM>>>(xH, xL, wqdH, wqdL, nullptr, xqH, xqL,
        4096, 2048, 2048, 2048, 1536,
        wkvH, wkvL, cbH, cbL, 1536, 512);
    // 2) fused: Q = Xq@Wqu^T  +  K[h] = C@kup[h]  +  V[h] = C@vup[h] (transposed)
    gemm_qkv<<<1536, 256, GEMM_SMEM>>>(xqH, xqL, wquH, wquL, qH, qL,
                                       cbH, cbL, kuH, kuL, kH, kL,
                                       vuH, vuL, vtH, vtL);
    // 3) attention -> AO planes (heavy-first scheduling)
    flash_tc<<<dim3(16, 16, 2), 256, FLASH_SMEM>>>(qH, qL, kH, kL, vtH, vtL, aoH, aoL);
    // 4) out = AO @ Wo^T (fp32)
    gemm_tc<0><<<dim3(16, 32), 256, GEMM_SMEM>>>(aoH, aoL, woH, woL, out, nullptr, nullptr,
        4096, 2048, 2048, 2048, 2048,
        nullptr, nullptr, nullptr, nullptr, 1 << 30, 0);
}

// round 9
// speedup vs baseline: 1.4896x; 1.4896x over previous
#include <cuda_runtime.h>
#include <cuda_bf16.h>
#include <math.h>
#include <stdint.h>

// ---------------- scratch (device globals; no allocations allowed) -----------
__device__ __nv_bfloat16 g_Xh[4096 * 2048],  g_Xl[4096 * 2048];
__device__ __nv_bfloat16 g_Xqh[4096 * 1536], g_Xql[4096 * 1536];
__device__ __nv_bfloat16 g_Cbh[4096 * 512],  g_Cbl[4096 * 512];
__device__ __nv_bfloat16 g_Qh[4096 * 2048],  g_Ql[4096 * 2048];
__device__ __nv_bfloat16 g_Kh[16 * 4096 * 128], g_Kl[16 * 4096 * 128];
__device__ __nv_bfloat16 g_Vth[16 * 128 * 4096], g_Vtl[16 * 128 * 4096];
__device__ __nv_bfloat16 g_AOh[4096 * 2048], g_AOl[4096 * 2048];

__device__ __nv_bfloat16 g_Wqd_hi[1536 * 2048], g_Wqd_lo[1536 * 2048];
__device__ __nv_bfloat16 g_Wqu_hi[2048 * 1536], g_Wqu_lo[2048 * 1536];
__device__ __nv_bfloat16 g_Wkvd_hi[512 * 2048], g_Wkvd_lo[512 * 2048];
__device__ __nv_bfloat16 g_Wo_hi[2048 * 2048], g_Wo_lo[2048 * 2048];
__device__ __nv_bfloat16 g_kupT_hi[16 * 128 * 512], g_kupT_lo[16 * 128 * 512];
__device__ __nv_bfloat16 g_vupT_hi[16 * 128 * 512], g_vupT_lo[16 * 128 * 512];

// ---------------- prep kernels ------------------------------------------------
__global__ void conv_plain4(const float* __restrict__ in, __nv_bfloat16* __restrict__ hi,
                            __nv_bfloat16* __restrict__ lo, int n4)
{
    int i = blockIdx.x * blockDim.x + threadIdx.x;
    if (i >= n4) return;
    float4 v = ((const float4*)in)[i];
    __nv_bfloat16 h0 = __float2bfloat16(v.x), h1 = __float2bfloat16(v.y);
    __nv_bfloat16 h2 = __float2bfloat16(v.z), h3 = __float2bfloat16(v.w);
    __nv_bfloat162 hh[2] = {__halves2bfloat162(h0, h1), __halves2bfloat162(h2, h3)};
    __nv_bfloat162 ll[2] = {
        __halves2bfloat162(__float2bfloat16(v.x - __bfloat162float(h0)),
                           __float2bfloat16(v.y - __bfloat162float(h1))),
        __halves2bfloat162(__float2bfloat16(v.z - __bfloat162float(h2)),
                           __float2bfloat16(v.w - __bfloat162float(h3)))};
    *(uint2*)(hi + i * 4) = *(uint2*)hh;
    *(uint2*)(lo + i * 4) = *(uint2*)ll;
}

// in: [Z][K][N] fp32 -> out planes [Z][N][K]
__global__ void conv_transpose(const float* __restrict__ in, __nv_bfloat16* __restrict__ hi,
                               __nv_bfloat16* __restrict__ lo, int Z, int K, int N)
{
    long i = (long)blockIdx.x * blockDim.x + threadIdx.x;
    long total = (long)Z * K * N;
    if (i >= total) return;
    int n = (int)(i % N);
    long t = i / N;
    int k = (int)(t % K);
    int z = (int)(t / K);
    float x = in[i];
    __nv_bfloat16 h = __float2bfloat16(x);
    long o = ((long)z * N + n) * K + k;
    hi[o] = h;
    lo[o] = __float2bfloat16(x - __bfloat162float(h));
}

// ---------------- shared helpers ---------------------------------------------
__device__ __forceinline__ uint32_t su(const void* p) {
    return (uint32_t)__cvta_generic_to_shared(p);
}
__device__ __forceinline__ void ldsm4(uint32_t* r, uint32_t addr) {
    asm volatile("ldmatrix.sync.aligned.m8n8.x4.shared.b16 {%0,%1,%2,%3}, [%4];"
                 : "=r"(r[0]), "=r"(r[1]), "=r"(r[2]), "=r"(r[3]) : "r"(addr));
}
__device__ __forceinline__ void mma16816(float* c, const uint32_t* a, const uint32_t* b) {
    asm volatile("mma.sync.aligned.m16n8k16.row.col.f32.bf16.bf16.f32 "
                 "{%0,%1,%2,%3}, {%4,%5,%6,%7}, {%8,%9}, {%0,%1,%2,%3};"
                 : "+f"(c[0]), "+f"(c[1]), "+f"(c[2]), "+f"(c[3])
                 : "r"(a[0]), "r"(a[1]), "r"(a[2]), "r"(a[3]), "r"(b[0]), "r"(b[1]));
}
__device__ __forceinline__ void cpa16(uint32_t dst, const void* src) {
    asm volatile("cp.async.cg.shared.global [%0], [%1], 16;" :: "r"(dst), "l"(src));
}
__device__ __forceinline__ uint32_t pack2(__nv_bfloat16 a, __nv_bfloat16 b) {
    __nv_bfloat162 t = __halves2bfloat162(a, b);
    return *(uint32_t*)&t;
}

// ---------------- bf16x3 mma.sync GEMM (all-plane, NS=2, 2 CTAs/SM) -----------
#define BM 128
#define BN 128
#define BK 32
#define LDSS 40
#define PLANE_ELE (128 * LDSS)
#define PLANE_BYTES (PLANE_ELE * 2)
#define STAGE_BYTES (4 * PLANE_BYTES)
#define NS 2
#define GEMM_SMEM (NS * STAGE_BYTES)     // 81920 -> 2 CTAs/SM

// EPI: 0 = fp32 C; 1 = bf16 hi/lo planes row-major (with merged-N support)
template <int EPI>
__global__ __launch_bounds__(256, 2)
void gemm_tc(const __nv_bfloat16* __restrict__ Ahi, const __nv_bfloat16* __restrict__ Alo,
             const __nv_bfloat16* __restrict__ Bhi, const __nv_bfloat16* __restrict__ Blo,
             float* __restrict__ C,
             __nv_bfloat16* __restrict__ Ohi, __nv_bfloat16* __restrict__ Olo,
             int M, int N, int K, int lda, int ldc,
             const __nv_bfloat16* __restrict__ B2hi, const __nv_bfloat16* __restrict__ B2lo,
             __nv_bfloat16* __restrict__ O2hi, __nv_bfloat16* __restrict__ O2lo,
             int nSplit, int ldc2)
{
    extern __shared__ __nv_bfloat16 smem[];

    const int tid = threadIdx.x;
    const int mBase = blockIdx.y * BM;
    int nBase = blockIdx.x * BN;

    const __nv_bfloat16 *BhiL, *BloL;
    __nv_bfloat16 *OhiL, *OloL;
    int ldcL = ldc;
    if (EPI == 1 && nBase >= nSplit) {
        BhiL = B2hi; BloL = B2lo; OhiL = O2hi; OloL = O2lo;
        nBase -= nSplit; ldcL = ldc2;
    } else {
        BhiL = Bhi; BloL = Blo; OhiL = Ohi; OloL = Olo;
    }

    const int ldRow = tid >> 1;
    const int ldCol = (tid & 1) * 16;
    const uint32_t stsB = (uint32_t)(ldRow * LDSS + ldCol) * 2;

    const int lane = tid & 31;
    const int wid = tid >> 5;
    const int wm = wid >> 2;
    const int wn = wid & 3;
    const int aRowL = wm * 64 + (lane & 15);
    const int aKL = ((lane >> 4) << 3);
    const int bRowL = wn * 32 + ((lane >> 4) << 3) + (lane & 7);
    const int bKL = ((lane >> 3) & 1) << 3;

    const uint32_t smemBase = su(smem);
    const int nt = K / BK;

    const __nv_bfloat16* pAh = Ahi + (long)(mBase + ldRow) * lda + ldCol;
    const __nv_bfloat16* pAl = Alo + (long)(mBase + ldRow) * lda + ldCol;
    const __nv_bfloat16* pBh = BhiL + (long)(nBase + ldRow) * K + ldCol;
    const __nv_bfloat16* pBl = BloL + (long)(nBase + ldRow) * K + ldCol;

    auto loadStage = [&](int s, int kt) {
        const uint32_t d = smemBase + s * STAGE_BYTES + stsB;
        const long off = (long)kt * BK;
        cpa16(d, pAh + off); cpa16(d + 16, pAh + off + 8);
        cpa16(d + PLANE_BYTES, pAl + off); cpa16(d + PLANE_BYTES + 16, pAl + off + 8);
        cpa16(d + 2 * PLANE_BYTES, pBh + off); cpa16(d + 2 * PLANE_BYTES + 16, pBh + off + 8);
        cpa16(d + 3 * PLANE_BYTES, pBl + off); cpa16(d + 3 * PLANE_BYTES + 16, pBl + off + 8);
    };

    float acc[4][4][4];
#pragma unroll
    for (int i = 0; i < 4; i++)
#pragma unroll
        for (int j = 0; j < 4; j++)
#pragma unroll
            for (int k = 0; k < 4; k++) acc[i][j][k] = 0.f;

    loadStage(0, 0);
    asm volatile("cp.async.commit_group;" ::: "memory");

    for (int kt = 0; kt < nt; kt++) {
        asm volatile("cp.async.wait_group 0;" ::: "memory");
        __syncthreads();

        if (kt + 1 < nt) {
            loadStage((kt + 1) & 1, kt + 1);
            asm volatile("cp.async.commit_group;" ::: "memory");
        }

        const uint32_t sAh = smemBase + (kt & 1) * STAGE_BYTES;
        const uint32_t sAl = sAh + PLANE_BYTES;
        const uint32_t sBh = sAh + 2 * PLANE_BYTES;
        const uint32_t sBl = sAh + 3 * PLANE_BYTES;

#pragma unroll
        for (int ks = 0; ks < BK; ks += 16) {
            uint32_t Ah[4][4], Al[4][4];
#pragma unroll
            for (int mb = 0; mb < 4; mb++) {
                const uint32_t off = ((aRowL + mb * 16) * LDSS + aKL + ks) * 2;
                ldsm4(Ah[mb], sAh + off);
                ldsm4(Al[mb], sAl + off);
            }
            uint32_t Bh[4][2], Bl[4][2];
#pragma unroll
            for (int nb2 = 0; nb2 < 2; nb2++) {
                const uint32_t off = ((bRowL + nb2 * 16) * LDSS + bKL + ks) * 2;
                uint32_t rg[4];
                ldsm4(rg, sBh + off);
                Bh[nb2 * 2][0] = rg[0]; Bh[nb2 * 2][1] = rg[1];
                Bh[nb2 * 2 + 1][0] = rg[2]; Bh[nb2 * 2 + 1][1] = rg[3];
                ldsm4(rg, sBl + off);
                Bl[nb2 * 2][0] = rg[0]; Bl[nb2 * 2][1] = rg[1];
                Bl[nb2 * 2 + 1][0] = rg[2]; Bl[nb2 * 2 + 1][1] = rg[3];
            }
#pragma unroll
            for (int mb = 0; mb < 4; mb++)
#pragma unroll
                for (int nb = 0; nb < 4; nb++) {
                    mma16816(acc[mb][nb], Ah[mb], Bh[nb]);
                    mma16816(acc[mb][nb], Ah[mb], Bl[nb]);
                    mma16816(acc[mb][nb], Al[mb], Bh[nb]);
                }
        }
        __syncthreads();
    }

#pragma unroll
    for (int mb = 0; mb < 4; mb++) {
        const int r = mBase + wm * 64 + mb * 16 + (lane >> 2);
#pragma unroll
        for (int nb = 0; nb < 4; nb++) {
            const int cc = nBase + wn * 32 + nb * 8 + (lane & 3) * 2;
            float v0 = acc[mb][nb][0], v1 = acc[mb][nb][1];
            float v2 = acc[mb][nb][2], v3 = acc[mb][nb][3];
            if (EPI == 0) {
                *(float2*)&C[(long)r * ldcL + cc] = make_float2(v0, v1);
                *(float2*)&C[(long)(r + 8) * ldcL + cc] = make_float2(v2, v3);
            } else {
                __nv_bfloat16 h0 = __float2bfloat16(v0), h1 = __float2bfloat16(v1);
                __nv_bfloat16 h2 = __float2bfloat16(v2), h3 = __float2bfloat16(v3);
                __nv_bfloat16 l0 = __float2bfloat16(v0 - __bfloat162float(h0));
                __nv_bfloat16 l1 = __float2bfloat16(v1 - __bfloat162float(h1));
                __nv_bfloat16 l2 = __float2bfloat16(v2 - __bfloat162float(h2));
                __nv_bfloat16 l3 = __float2bfloat16(v3 - __bfloat162float(h3));
                *(__nv_bfloat162*)&OhiL[(long)r * ldcL + cc] = __halves2bfloat162(h0, h1);
                *(__nv_bfloat162*)&OhiL[(long)(r + 8) * ldcL + cc] = __halves2bfloat162(h2, h3);
                *(__nv_bfloat162*)&OloL[(long)r * ldcL + cc] = __halves2bfloat162(l0, l1);
                *(__nv_bfloat162*)&OloL[(long)(r + 8) * ldcL + cc] = __halves2bfloat162(l2, l3);
            }
        }
    }
}

// ---------------- fused K-up + V-up GEMM (homogeneous, 1024 CTAs) -------------
// bid < 512 : K[h] = C @ kupT[h]^T, row-major plane epilogue [h][row][d]
// else      : V[h] = C @ vupT[h]^T, TRANSPOSED plane epilogue [h][d][row]
// Same A, lda=512, Kd=512, identical mainloop -> uniform CTA duration.
__global__ __launch_bounds__(256, 2)
void gemm_kv(const __nv_bfloat16* __restrict__ cbH, const __nv_bfloat16* __restrict__ cbL,
             const __nv_bfloat16* __restrict__ kuH, const __nv_bfloat16* __restrict__ kuL,
             __nv_bfloat16* __restrict__ kH, __nv_bfloat16* __restrict__ kL,
             const __nv_bfloat16* __restrict__ vuH, const __nv_bfloat16* __restrict__ vuL,
             __nv_bfloat16* __restrict__ vtH, __nv_bfloat16* __restrict__ vtL)
{
    extern __shared__ __nv_bfloat16 smem[];
    const int tid = threadIdx.x;
    const int bid = blockIdx.x;
    const bool isV = bid >= 512;
    const int t = bid & 511;
    const int h = t >> 5;
    const int mBase = (t & 31) * 128;

    const __nv_bfloat16* Bhi = (isV ? vuH : kuH) + (long)h * 128 * 512;
    const __nv_bfloat16* Blo = (isV ? vuL : kuL) + (long)h * 128 * 512;
    __nv_bfloat16* Ohi = isV ? (vtH + (long)h * 128 * 4096) : (kH + (long)h * 4096 * 128);
    __nv_bfloat16* Olo = isV ? (vtL + (long)h * 128 * 4096) : (kL + (long)h * 4096 * 128);
    const int ldc = isV ? 4096 : 128;

    const int ldRow = tid >> 1;
    const int ldCol = (tid & 1) * 16;
    const uint32_t stsB = (uint32_t)(ldRow * LDSS + ldCol) * 2;

    const int lane = tid & 31;
    const int wid = tid >> 5;
    const int wm = wid >> 2;
    const int wn = wid & 3;
    const int aRowL = wm * 64 + (lane & 15);
    const int aKL = ((lane >> 4) << 3);
    const int bRowL = wn * 32 + ((lane >> 4) << 3) + (lane & 7);
    const int bKL = ((lane >> 3) & 1) << 3;

    const uint32_t smemBase = su(smem);
    const int nt = 512 / BK;   // 16

    const __nv_bfloat16* pAh = cbH + (long)(mBase + ldRow) * 512 + ldCol;
    const __nv_bfloat16* pAl = cbL + (long)(mBase + ldRow) * 512 + ldCol;
    const __nv_bfloat16* pBh = Bhi + (long)ldRow * 512 + ldCol;
    const __nv_bfloat16* pBl = Blo + (long)ldRow * 512 + ldCol;

    auto loadStage = [&](int s, int kt) {
        const uint32_t d = smemBase + s * STAGE_BYTES + stsB;
        const long off = (long)kt * BK;
        cpa16(d, pAh + off); cpa16(d + 16, pAh + off + 8);
        cpa16(d + PLANE_BYTES, pAl + off); cpa16(d + PLANE_BYTES + 16, pAl + off + 8);
        cpa16(d + 2 * PLANE_BYTES, pBh + off); cpa16(d + 2 * PLANE_BYTES + 16, pBh + off + 8);
        cpa16(d + 3 * PLANE_BYTES, pBl + off); cpa16(d + 3 * PLANE_BYTES + 16, pBl + off + 8);
    };

    float acc[4][4][4];
#pragma unroll
    for (int i = 0; i < 4; i++)
#pragma unroll
        for (int j = 0; j < 4; j++)
#pragma unroll
            for (int k = 0; k < 4; k++) acc[i][j][k] = 0.f;

    loadStage(0, 0);
    asm volatile("cp.async.commit_group;" ::: "memory");

    for (int kt = 0; kt < nt; kt++) {
        asm volatile("cp.async.wait_group 0;" ::: "memory");
        __syncthreads();

        if (kt + 1 < nt) {
            loadStage((kt + 1) & 1, kt + 1);
            asm volatile("cp.async.commit_group;" ::: "memory");
        }

        const uint32_t sAh = smemBase + (kt & 1) * STAGE_BYTES;
        const uint32_t sAl = sAh + PLANE_BYTES;
        const uint32_t sBh = sAh + 2 * PLANE_BYTES;
        const uint32_t sBl = sAh + 3 * PLANE_BYTES;

#pragma unroll
        for (int ks = 0; ks < BK; ks += 16) {
            uint32_t Ah[4][4], Al[4][4];
#pragma unroll
            for (int mb = 0; mb < 4; mb++) {
                const uint32_t off = ((aRowL + mb * 16) * LDSS + aKL + ks) * 2;
                ldsm4(Ah[mb], sAh + off);
                ldsm4(Al[mb], sAl + off);
            }
            uint32_t Bh[4][2], Bl[4][2];
#pragma unroll
            for (int nb2 = 0; nb2 < 2; nb2++) {
                const uint32_t off = ((bRowL + nb2 * 16) * LDSS + bKL + ks) * 2;
                uint32_t rg[4];
                ldsm4(rg, sBh + off);
                Bh[nb2 * 2][0] = rg[0]; Bh[nb2 * 2][1] = rg[1];
                Bh[nb2 * 2 + 1][0] = rg[2]; Bh[nb2 * 2 + 1][1] = rg[3];
                ldsm4(rg, sBl + off);
                Bl[nb2 * 2][0] = rg[0]; Bl[nb2 * 2][1] = rg[1];
                Bl[nb2 * 2 + 1][0] = rg[2]; Bl[nb2 * 2 + 1][1] = rg[3];
            }
#pragma unroll
            for (int mb = 0; mb < 4; mb++)
#pragma unroll
                for (int nb = 0; nb < 4; nb++) {
                    mma16816(acc[mb][nb], Ah[mb], Bh[nb]);
                    mma16816(acc[mb][nb], Ah[mb], Bl[nb]);
                    mma16816(acc[mb][nb], Al[mb], Bh[nb]);
                }
        }
        __syncthreads();
    }

#pragma unroll
    for (int mb = 0; mb < 4; mb++) {
        const int r = mBase + wm * 64 + mb * 16 + (lane >> 2);
#pragma unroll
        for (int nb = 0; nb < 4; nb++) {
            const int cc = wn * 32 + nb * 8 + (lane & 3) * 2;
            float v0 = acc[mb][nb][0], v1 = acc[mb][nb][1];
            float v2 = acc[mb][nb][2], v3 = acc[mb][nb][3];
            __nv_bfloat16 h0 = __float2bfloat16(v0), h1 = __float2bfloat16(v1);
            __nv_bfloat16 h2 = __float2bfloat16(v2), h3 = __float2bfloat16(v3);
            __nv_bfloat16 l0 = __float2bfloat16(v0 - __bfloat162float(h0));
            __nv_bfloat16 l1 = __float2bfloat16(v1 - __bfloat162float(h1));
            __nv_bfloat16 l2 = __float2bfloat16(v2 - __bfloat162float(h2));
            __nv_bfloat16 l3 = __float2bfloat16(v3 - __bfloat162float(h3));
            if (!isV) {
                *(__nv_bfloat162*)&Ohi[(long)r * ldc + cc] = __halves2bfloat162(h0, h1);
                *(__nv_bfloat162*)&Ohi[(long)(r + 8) * ldc + cc] = __halves2bfloat162(h2, h3);
                *(__nv_bfloat162*)&Olo[(long)r * ldc + cc] = __halves2bfloat162(l0, l1);
                *(__nv_bfloat162*)&Olo[(long)(r + 8) * ldc + cc] = __halves2bfloat162(l2, l3);
            } else {
                Ohi[(long)cc * ldc + r] = h0;
                Ohi[(long)(cc + 1) * ldc + r] = h1;
                Ohi[(long)cc * ldc + r + 8] = h2;
                Ohi[(long)(cc + 1) * ldc + r + 8] = h3;
                Olo[(long)cc * ldc + r] = l0;
                Olo[(long)(cc + 1) * ldc + r] = l1;
                Olo[(long)cc * ldc + r + 8] = l2;
                Olo[(long)(cc + 1) * ldc + r + 8] = l3;
            }
        }
    }
}

// ---------------- tensor-core flash attention --------------------------------
#define FQ_S 136
#define FV_S 72
#define FQH_O 0
#define FQL_O 17408
#define FK_O 34816
#define FV_O 69632
#define FLASH_SMEM (106496 * 2)
#define SCALE_F 0.08838834764831845f

__global__ __launch_bounds__(256)
void flash_tc(const __nv_bfloat16* __restrict__ Qh, const __nv_bfloat16* __restrict__ Ql,
              const __nv_bfloat16* __restrict__ Kh, const __nv_bfloat16* __restrict__ Kl,
              const __nv_bfloat16* __restrict__ Vth, const __nv_bfloat16* __restrict__ Vtl,
              __nv_bfloat16* __restrict__ AOh, __nv_bfloat16* __restrict__ AOl)
{
    extern __shared__ __nv_bfloat16 fsm[];
    // LPT: heavy q-tiles (more kv iterations) dispatched first
    const int qt = (int)gridDim.x - 1 - (int)blockIdx.x;
    const int h = blockIdx.y, b = blockIdx.z;
    const int tid = threadIdx.x, lane = tid & 31, w = tid >> 5;
    const float slope = exp2f(-0.5f * (float)(h + 1));
    const int nt = 2 * qt + 2;

    const uint32_t fb = su(fsm);

    {
        const int r = tid >> 1, cb = (tid & 1) * 64;
        const __nv_bfloat16* sh = Qh + (long)(b * 2048 + qt * 128 + r) * 2048 + h * 128 + cb;
        const __nv_bfloat16* sl = Ql + (long)(b * 2048 + qt * 128 + r) * 2048 + h * 128 + cb;
        const uint32_t dh = fb + (FQH_O + r * FQ_S + cb) * 2;
        const uint32_t dl = fb + (FQL_O + r * FQ_S + cb) * 2;
#pragma unroll
        for (int u = 0; u < 8; u++) { cpa16(dh + u * 16, sh + u * 8); cpa16(dl + u * 16, sl + u * 8); }
    }
    auto loadKV = [&](int stg, int jt) {
        const int kr = tid >> 2, kcb = (tid & 3) * 32;
        const long krow = (long)h * 4096 + b * 2048 + jt * 64 + kr;
        const __nv_bfloat16* skh = Kh + krow * 128 + kcb;
        const __nv_bfloat16* skl = Kl + krow * 128 + kcb;
        const uint32_t kdh = fb + (FK_O + stg * 17408 + kr * FQ_S + kcb) * 2;
        const uint32_t kdl = kdh + 8704 * 2;
#pragma unroll
        for (int u = 0; u < 4; u++) { cpa16(kdh + u * 16, skh + u * 8); cpa16(kdl + u * 16, skl + u * 8); }
        const int vr = tid >> 1, vcb = (tid & 1) * 32;
        const long vrow = (long)h * 128 + vr;
        const __nv_bfloat16* svh = Vth + vrow * 4096 + b * 2048 + jt * 64 + vcb;
        const __nv_bfloat16* svl = Vtl + vrow * 4096 + b * 2048 + jt * 64 + vcb;
        const uint32_t vdh = fb + (FV_O + stg * 18432 + vr * FV_S + vcb) * 2;
        const uint32_t vdl = vdh + 9216 * 2;
#pragma unroll
        for (int u = 0; u < 4; u++) { cpa16(vdh + u * 16, svh + u * 8); cpa16(vdl + u * 16, svl + u * 8); }
    };
    loadKV(0, 0);
    asm volatile("cp.async.commit_group;");

    const int aRow = w * 16 + (lane & 15);
    const int aCol8 = (lane >> 4) << 3;
    const int bRow8 = ((lane >> 4) << 3) + (lane & 7);
    const int bCol8 = ((lane >> 3) & 1) << 3;

    float m0 = -1e30f, m1 = -1e30f, l0 = 0.f, l1 = 0.f;
    float o[16][4];
#pragma unroll
    for (int i = 0; i < 16; i++)
#pragma unroll
        for (int j = 0; j < 4; j++) o[i][j] = 0.f;

    const int grow0 = qt * 128 + w * 16 + (lane >> 2);

    for (int jt = 0; jt < nt; jt++) {
        const int cur = jt & 1;
        if (jt > 0) __syncthreads();
        if (jt + 1 < nt) {
            loadKV(cur ^ 1, jt + 1);
            asm volatile("cp.async.commit_group;");
            asm volatile("cp.async.wait_group 1;");
        } else {
            asm volatile("cp.async.wait_group 0;");
        }
        __syncthreads();

        const uint32_t bKH = fb + (FK_O + cur * 17408) * 2;
        const uint32_t bKL = bKH + 8704 * 2;
        const uint32_t bVH = fb + (FV_O + cur * 18432) * 2;
        const uint32_t bVL = bVH + 9216 * 2;

        float s[8][4];
#pragma unroll
        for (int i = 0; i < 8; i++)
#pragma unroll
            for (int j = 0; j < 4; j++) s[i][j] = 0.f;

#pragma unroll
        for (int ks = 0; ks < 8; ks++) {
            uint32_t qh[4], ql[4];
            const uint32_t aoff = (uint32_t)(aRow * FQ_S + ks * 16 + aCol8) * 2;
            ldsm4(qh, fb + FQH_O * 2 + aoff);
            ldsm4(ql, fb + FQL_O * 2 + aoff);
#pragma unroll
            for (int nb2 = 0; nb2 < 4; nb2++) {
                const uint32_t boff = (uint32_t)((nb2 * 16 + bRow8) * FQ_S + ks * 16 + bCol8) * 2;
                uint32_t kh[4], kl[4];
                ldsm4(kh, bKH + boff);
                ldsm4(kl, bKL + boff);
                mma16816(s[2 * nb2],     qh, &kh[0]);
                mma16816(s[2 * nb2],     qh, &kl[0]);
                mma16816(s[2 * nb2],     ql, &kh[0]);
                mma16816(s[2 * nb2 + 1], qh, &kh[2]);
                mma16816(s[2 * nb2 + 1], qh, &kl[2]);
                mma16816(s[2 * nb2 + 1], ql, &kh[2]);
            }
        }

#pragma unroll
        for (int nb = 0; nb < 8; nb++) {
#pragma unroll
            for (int j = 0; j < 2; j++) {
                const int gc = jt * 64 + nb * 8 + (lane & 3) * 2 + j;
                float v = s[nb][j];
                s[nb][j] = (gc > grow0) ? -1e30f
                          : v * SCALE_F - slope * (float)(grow0 - gc);
                float v2 = s[nb][2 + j];
                s[nb][2 + j] = (gc > grow0 + 8) ? -1e30f
                          : v2 * SCALE_F - slope * (float)(grow0 + 8 - gc);
            }
        }

        float mx0 = -1e30f, mx1 = -1e30f;
#pragma unroll
        for (int nb = 0; nb < 8; nb++) {
            mx0 = fmaxf(mx0, fmaxf(s[nb][0], s[nb][1]));
            mx1 = fmaxf(mx1, fmaxf(s[nb][2], s[nb][3]));
        }
        mx0 = fmaxf(mx0, __shfl_xor_sync(0xffffffffu, mx0, 1));
        mx0 = fmaxf(mx0, __shfl_xor_sync(0xffffffffu, mx0, 2));
        mx1 = fmaxf(mx1, __shfl_xor_sync(0xffffffffu, mx1, 1));
        mx1 = fmaxf(mx1, __shfl_xor_sync(0xffffffffu, mx1, 2));
        const float mn0 = fmaxf(m0, mx0), mn1 = fmaxf(m1, mx1);
        const float al0 = __expf(m0 - mn0), al1 = __expf(m1 - mn1);
        m0 = mn0; m1 = mn1;

        float sum0 = 0.f, sum1 = 0.f;
#pragma unroll
        for (int nb = 0; nb < 8; nb++) {
            s[nb][0] = __expf(s[nb][0] - mn0); sum0 += s[nb][0];
            s[nb][1] = __expf(s[nb][1] - mn0); sum0 += s[nb][1];
            s[nb][2] = __expf(s[nb][2] - mn1); sum1 += s[nb][2];
            s[nb][3] = __expf(s[nb][3] - mn1); sum1 += s[nb][3];
        }
        sum0 += __shfl_xor_sync(0xffffffffu, sum0, 1);
        sum0 += __shfl_xor_sync(0xffffffffu, sum0, 2);
        sum1 += __shfl_xor_sync(0xffffffffu, sum1, 1);
        sum1 += __shfl_xor_sync(0xffffffffu, sum1, 2);
        l0 = l0 * al0 + sum0;
        l1 = l1 * al1 + sum1;

#pragma unroll
        for (int nb = 0; nb < 16; nb++) {
            o[nb][0] *= al0; o[nb][1] *= al0;
            o[nb][2] *= al1; o[nb][3] *= al1;
        }

        uint32_t ph[4][4], pl[4][4];
#pragma unroll
        for (int kb = 0; kb < 4; kb++) {
#pragma unroll
            for (int q = 0; q < 4; q++) {
                const float x = s[2 * kb + (q >> 1)][(q & 1) * 2 + 0];
                const float y = s[2 * kb + (q >> 1)][(q & 1) * 2 + 1];
                const __nv_bfloat16 hx = __float2bfloat16(x), hy = __float2bfloat16(y);
                ph[kb][q] = pack2(hx, hy);
                pl[kb][q] = pack2(__float2bfloat16(x - __bfloat162float(hx)),
                                  __float2bfloat16(y - __bfloat162float(hy)));
            }
        }

#pragma unroll
        for (int kb = 0; kb < 4; kb++) {
#pragma unroll
            for (int nb2 = 0; nb2 < 8; nb2++) {
                const uint32_t voff = (uint32_t)((nb2 * 16 + bRow8) * FV_S + kb * 16 + bCol8) * 2;
                uint32_t vh[4], vl[4];
                ldsm4(vh, bVH + voff);
                ldsm4(vl, bVL + voff);
                mma16816(o[2 * nb2],     ph[kb], &vh[0]);
                mma16816(o[2 * nb2],     ph[kb], &vl[0]);
                mma16816(o[2 * nb2],     pl[kb], &vh[0]);
                mma16816(o[2 * nb2 + 1], ph[kb], &vh[2]);
                mma16816(o[2 * nb2 + 1], ph[kb], &vl[2]);
                mma16816(o[2 * nb2 + 1], pl[kb], &vh[2]);
            }
        }
    }

    const float inv0 = 1.f / l0, inv1 = 1.f / l1;
    const long row0 = (long)b * 2048 + qt * 128 + w * 16 + (lane >> 2);
#pragma unroll
    for (int nb = 0; nb < 16; nb++) {
        const int c = h * 128 + nb * 8 + (lane & 3) * 2;
        float x0 = o[nb][0] * inv0, x1 = o[nb][1] * inv0;
        float x2 = o[nb][2] * inv1, x3 = o[nb][3] * inv1;
        __nv_bfloat16 h0 = __float2bfloat16(x0), h1 = __float2bfloat16(x1);
        __nv_bfloat16 h2 = __float2bfloat16(x2), h3 = __float2bfloat16(x3);
        *(__nv_bfloat162*)&AOh[row0 * 2048 + c] = __halves2bfloat162(h0, h1);
        *(__nv_bfloat162*)&AOh[(row0 + 8) * 2048 + c] = __halves2bfloat162(h2, h3);
        *(__nv_bfloat162*)&AOl[row0 * 2048 + c] =
            __halves2bfloat162(__float2bfloat16(x0 - __bfloat162float(h0)),
                               __float2bfloat16(x1 - __bfloat162float(h1)));
        *(__nv_bfloat162*)&AOl[(row0 + 8) * 2048 + c] =
            __halves2bfloat162(__float2bfloat16(x2 - __bfloat162float(h2)),
                               __float2bfloat16(x3 - __bfloat162float(h3)));
    }
}

// ---------------- launch ------------------------------------------------------
extern "C" void kernel_launch(void* const* d_in, const int* in_sizes, int n_in,
                              void* d_out, int out_size)
{
    const float* X    = (const float*)d_in[0];
    const float* Wqd  = (const float*)d_in[1];
    const float* Wqu  = (const float*)d_in[2];
    const float* Wkvd = (const float*)d_in[3];
    const float* kup  = (const float*)d_in[4];
    const float* vup  = (const float*)d_in[5];
    const float* Wo   = (const float*)d_in[6];
    float* out = (float*)d_out;

    __nv_bfloat16 *xH, *xL, *xqH, *xqL, *cbH, *cbL, *qH, *qL, *kH, *kL, *vtH, *vtL, *aoH, *aoL;
    cudaGetSymbolAddress((void**)&xH, g_Xh);   cudaGetSymbolAddress((void**)&xL, g_Xl);
    cudaGetSymbolAddress((void**)&xqH, g_Xqh); cudaGetSymbolAddress((void**)&xqL, g_Xql);
    cudaGetSymbolAddress((void**)&cbH, g_Cbh); cudaGetSymbolAddress((void**)&cbL, g_Cbl);
    cudaGetSymbolAddress((void**)&qH, g_Qh);   cudaGetSymbolAddress((void**)&qL, g_Ql);
    cudaGetSymbolAddress((void**)&kH, g_Kh);   cudaGetSymbolAddress((void**)&kL, g_Kl);
    cudaGetSymbolAddress((void**)&vtH, g_Vth); cudaGetSymbolAddress((void**)&vtL, g_Vtl);
    cudaGetSymbolAddress((void**)&aoH, g_AOh); cudaGetSymbolAddress((void**)&aoL, g_AOl);

    __nv_bfloat16 *wqdH, *wqdL, *wquH, *wquL, *wkvH, *wkvL, *woH, *woL;
    __nv_bfloat16 *kuH, *kuL, *vuH, *vuL;
    cudaGetSymbolAddress((void**)&wqdH, g_Wqd_hi); cudaGetSymbolAddress((void**)&wqdL, g_Wqd_lo);
    cudaGetSymbolAddress((void**)&wquH, g_Wqu_hi); cudaGetSymbolAddress((void**)&wquL, g_Wqu_lo);
    cudaGetSymbolAddress((void**)&wkvH, g_Wkvd_hi); cudaGetSymbolAddress((void**)&wkvL, g_Wkvd_lo);
    cudaGetSymbolAddress((void**)&woH, g_Wo_hi); cudaGetSymbolAddress((void**)&woL, g_Wo_lo);
    cudaGetSymbolAddress((void**)&kuH, g_kupT_hi); cudaGetSymbolAddress((void**)&kuL, g_kupT_lo);
    cudaGetSymbolAddress((void**)&vuH, g_vupT_hi); cudaGetSymbolAddress((void**)&vuL, g_vupT_lo);

    cudaFuncSetAttribute(gemm_tc<0>, cudaFuncAttributeMaxDynamicSharedMemorySize, GEMM_SMEM);
    cudaFuncSetAttribute(gemm_tc<1>, cudaFuncAttributeMaxDynamicSharedMemorySize, GEMM_SMEM);
    cudaFuncSetAttribute(gemm_kv, cudaFuncAttributeMaxDynamicSharedMemorySize, GEMM_SMEM);
    cudaFuncSetAttribute(flash_tc, cudaFuncAttributeMaxDynamicSharedMemorySize, FLASH_SMEM);

    // ---- prep: split everything into bf16 hi/lo planes (as R6) ----
    conv_plain4<<<(4096 * 2048 / 4 + 255) / 256, 256>>>(X, xH, xL, 4096 * 2048 / 4);
    conv_plain4<<<(1536 * 2048 / 4 + 255) / 256, 256>>>(Wqd, wqdH, wqdL, 1536 * 2048 / 4);
    conv_plain4<<<(2048 * 1536 / 4 + 255) / 256, 256>>>(Wqu, wquH, wquL, 2048 * 1536 / 4);
    conv_plain4<<<(512 * 2048 / 4 + 255) / 256, 256>>>(Wkvd, wkvH, wkvL, 512 * 2048 / 4);
    conv_plain4<<<(2048 * 2048 / 4 + 255) / 256, 256>>>(Wo, woH, woL, 2048 * 2048 / 4);
    conv_transpose<<<(16 * 512 * 128 + 255) / 256, 256>>>(kup, kuH, kuL, 16, 512, 128);
    conv_transpose<<<(16 * 512 * 128 + 255) / 256, 256>>>(vup, vuH, vuL, 16, 512, 128);

    // 1) [Xq | C] = X @ [Wqd | Wkvd]^T  (merged-N)
    gemm_tc<1><<<dim3(16, 32), 256, GEMM_SMEM>>>(xH, xL, wqdH, wqdL, nullptr, xqH, xqL,
        4096, 2048, 2048, 2048, 1536,
        wkvH, wkvL, cbH, cbL, 1536, 512);
    // 2) Q = Xq @ Wq_up^T -> planes
    gemm_tc<1><<<dim3(16, 32), 256, GEMM_SMEM>>>(xqH, xqL, wquH, wquL, nullptr, qH, qL,
        4096, 2048, 1536, 1536, 2048,
        nullptr, nullptr, nullptr, nullptr, 1 << 30, 0);
    // 3) fused K/V up-projections (homogeneous 1024-CTA launch)
    gemm_kv<<<1024, 256, GEMM_SMEM>>>(cbH, cbL, kuH, kuL, kH, kL, vuH, vuL, vtH, vtL);
    // 4) attention -> AO planes (LPT: heavy tiles first)
    flash_tc<<<dim3(16, 16, 2), 256, FLASH_SMEM>>>(qH, qL, kH, kL, vtH, vtL, aoH, aoL);
    // 5) out = AO @ Wo^T (fp32)
    gemm_tc<0><<<dim3(16, 32), 256, GEMM_SMEM>>>(aoH, aoL, woH, woL, out, nullptr, nullptr,
        4096, 2048, 2048, 2048, 2048,
        nullptr, nullptr, nullptr, nullptr, 1 << 30, 0);
}

// round 10
// speedup vs baseline: 1.9795x; 1.3289x over previous
#include <cuda_runtime.h>
#include <cuda_fp16.h>
#include <math.h>
#include <stdint.h>

// ---------------- scratch (device globals; no allocations allowed) -----------
// A-side activations: single fp16 plane. B-side (weights, K, V): fp16 hi/lo.
__device__ __half g_X[4096 * 2048];
__device__ __half g_Xq[4096 * 1536];
__device__ __half g_Cb[4096 * 512];
__device__ __half g_Q[4096 * 2048];
__device__ __half g_Kh[16 * 4096 * 128], g_Kl[16 * 4096 * 128];     // [h][row][d]
__device__ __half g_Vth[16 * 128 * 4096], g_Vtl[16 * 128 * 4096];   // [h][d][row]
__device__ __half g_AO[4096 * 2048];

__device__ __half g_Wqd_hi[1536 * 2048], g_Wqd_lo[1536 * 2048];
__device__ __half g_Wqu_hi[2048 * 1536], g_Wqu_lo[2048 * 1536];
__device__ __half g_Wkvd_hi[512 * 2048], g_Wkvd_lo[512 * 2048];
__device__ __half g_Wo_hi[2048 * 2048], g_Wo_lo[2048 * 2048];
__device__ __half g_kupT_hi[16 * 128 * 512], g_kupT_lo[16 * 128 * 512];
__device__ __half g_vupT_hi[16 * 128 * 512], g_vupT_lo[16 * 128 * 512];

// ---------------- prep kernels ------------------------------------------------
__global__ void conv_single4(const float* __restrict__ in, __half* __restrict__ out, int n4)
{
    int i = blockIdx.x * blockDim.x + threadIdx.x;
    if (i >= n4) return;
    float4 v = ((const float4*)in)[i];
    __half2 a = __halves2half2(__float2half_rn(v.x), __float2half_rn(v.y));
    __half2 b = __halves2half2(__float2half_rn(v.z), __float2half_rn(v.w));
    uint2 o;
    o.x = *(uint32_t*)&a; o.y = *(uint32_t*)&b;
    *(uint2*)(out + i * 4) = o;
}

__global__ void conv_pair4(const float* __restrict__ in, __half* __restrict__ hi,
                           __half* __restrict__ lo, int n4)
{
    int i = blockIdx.x * blockDim.x + threadIdx.x;
    if (i >= n4) return;
    float4 v = ((const float4*)in)[i];
    __half h0 = __float2half_rn(v.x), h1 = __float2half_rn(v.y);
    __half h2 = __float2half_rn(v.z), h3 = __float2half_rn(v.w);
    __half l0 = __float2half_rn(v.x - __half2float(h0));
    __half l1 = __float2half_rn(v.y - __half2float(h1));
    __half l2 = __float2half_rn(v.z - __half2float(h2));
    __half l3 = __float2half_rn(v.w - __half2float(h3));
    __half2 hh0 = __halves2half2(h0, h1), hh1 = __halves2half2(h2, h3);
    __half2 ll0 = __halves2half2(l0, l1), ll1 = __halves2half2(l2, l3);
    uint2 oh, ol;
    oh.x = *(uint32_t*)&hh0; oh.y = *(uint32_t*)&hh1;
    ol.x = *(uint32_t*)&ll0; ol.y = *(uint32_t*)&ll1;
    *(uint2*)(hi + i * 4) = oh;
    *(uint2*)(lo + i * 4) = ol;
}

// in: [Z][K][N] fp32 -> fp16 hi/lo planes [Z][N][K]
__global__ void conv_transpose(const float* __restrict__ in, __half* __restrict__ hi,
                               __half* __restrict__ lo, int Z, int K, int N)
{
    long i = (long)blockIdx.x * blockDim.x + threadIdx.x;
    long total = (long)Z * K * N;
    if (i >= total) return;
    int n = (int)(i % N);
    long t = i / N;
    int k = (int)(t % K);
    int z = (int)(t / K);
    float x = in[i];
    __half h = __float2half_rn(x);
    long o = ((long)z * N + n) * K + k;
    hi[o] = h;
    lo[o] = __float2half_rn(x - __half2float(h));
}

// ---------------- shared helpers ---------------------------------------------
__device__ __forceinline__ uint32_t su(const void* p) {
    return (uint32_t)__cvta_generic_to_shared(p);
}
__device__ __forceinline__ void ldsm4(uint32_t* r, uint32_t addr) {
    asm volatile("ldmatrix.sync.aligned.m8n8.x4.shared.b16 {%0,%1,%2,%3}, [%4];"
                 : "=r"(r[0]), "=r"(r[1]), "=r"(r[2]), "=r"(r[3]) : "r"(addr));
}
__device__ __forceinline__ void mma16816h(float* c, const uint32_t* a, const uint32_t* b) {
    asm volatile("mma.sync.aligned.m16n8k16.row.col.f32.f16.f16.f32 "
                 "{%0,%1,%2,%3}, {%4,%5,%6,%7}, {%8,%9}, {%0,%1,%2,%3};"
                 : "+f"(c[0]), "+f"(c[1]), "+f"(c[2]), "+f"(c[3])
                 : "r"(a[0]), "r"(a[1]), "r"(a[2]), "r"(a[3]), "r"(b[0]), "r"(b[1]));
}
__device__ __forceinline__ void cpa16(uint32_t dst, const void* src) {
    asm volatile("cp.async.cg.shared.global [%0], [%1], 16;" :: "r"(dst), "l"(src));
}
__device__ __forceinline__ uint32_t pack2h(__half a, __half b) {
    __half2 t = __halves2half2(a, b);
    return *(uint32_t*)&t;
}

// ---------------- fp16 2-term mma.sync GEMM (A single, B hi/lo) ---------------
#define BM 128
#define BN 128
#define BK 32
#define LDSS 40
#define PLANE_ELE (128 * LDSS)
#define PLANE_BYTES (PLANE_ELE * 2)      // 10240
#define STAGE_BYTES (3 * PLANE_BYTES)    // 30720: A, Bh, Bl
#define NS 2
#define GEMM_SMEM (NS * STAGE_BYTES)     // 61440 -> 2 CTAs/SM

// EPI: 0 = fp32 C out; 1 = single fp16 plane out (with merged-N support)
template <int EPI>
__global__ __launch_bounds__(256, 2)
void gemm_tc(const __half* __restrict__ A,
             const __half* __restrict__ Bhi, const __half* __restrict__ Blo,
             float* __restrict__ C, __half* __restrict__ O,
             int M, int N, int K, int lda, int ldc,
             const __half* __restrict__ B2hi, const __half* __restrict__ B2lo,
             __half* __restrict__ O2, int nSplit, int ldc2)
{
    extern __shared__ __half smem[];

    const int tid = threadIdx.x;
    const int mBase = blockIdx.y * BM;
    int nBase = blockIdx.x * BN;

    const __half *BhiL, *BloL;
    __half* OL;
    int ldcL = ldc;
    if (EPI == 1 && nBase >= nSplit) {
        BhiL = B2hi; BloL = B2lo; OL = O2;
        nBase -= nSplit; ldcL = ldc2;
    } else {
        BhiL = Bhi; BloL = Blo; OL = O;
    }

    const int ldRow = tid >> 1;
    const int ldCol = (tid & 1) * 16;
    const uint32_t stsB = (uint32_t)(ldRow * LDSS + ldCol) * 2;

    const int lane = tid & 31;
    const int wid = tid >> 5;
    const int wm = wid >> 2;
    const int wn = wid & 3;
    const int aRowL = wm * 64 + (lane & 15);
    const int aKL = ((lane >> 4) << 3);
    const int bRowL = wn * 32 + ((lane >> 4) << 3) + (lane & 7);
    const int bKL = ((lane >> 3) & 1) << 3;

    const uint32_t smemBase = su(smem);
    const int nt = K / BK;

    const __half* pA  = A + (long)(mBase + ldRow) * lda + ldCol;
    const __half* pBh = BhiL + (long)(nBase + ldRow) * K + ldCol;
    const __half* pBl = BloL + (long)(nBase + ldRow) * K + ldCol;

    auto loadStage = [&](int s, int kt) {
        const uint32_t d = smemBase + s * STAGE_BYTES + stsB;
        const long off = (long)kt * BK;
        cpa16(d, pA + off); cpa16(d + 16, pA + off + 8);
        cpa16(d + PLANE_BYTES, pBh + off); cpa16(d + PLANE_BYTES + 16, pBh + off + 8);
        cpa16(d + 2 * PLANE_BYTES, pBl + off); cpa16(d + 2 * PLANE_BYTES + 16, pBl + off + 8);
    };

    float acc[4][4][4];
#pragma unroll
    for (int i = 0; i < 4; i++)
#pragma unroll
        for (int j = 0; j < 4; j++)
#pragma unroll
            for (int k = 0; k < 4; k++) acc[i][j][k] = 0.f;

    loadStage(0, 0);
    asm volatile("cp.async.commit_group;" ::: "memory");

    for (int kt = 0; kt < nt; kt++) {
        asm volatile("cp.async.wait_group 0;" ::: "memory");
        __syncthreads();

        if (kt + 1 < nt) {
            loadStage((kt + 1) & 1, kt + 1);
            asm volatile("cp.async.commit_group;" ::: "memory");
        }

        const uint32_t sA  = smemBase + (kt & 1) * STAGE_BYTES;
        const uint32_t sBh = sA + PLANE_BYTES;
        const uint32_t sBl = sA + 2 * PLANE_BYTES;

#pragma unroll
        for (int ks = 0; ks < BK; ks += 16) {
            uint32_t Af[4][4];
#pragma unroll
            for (int mb = 0; mb < 4; mb++) {
                const uint32_t off = ((aRowL + mb * 16) * LDSS + aKL + ks) * 2;
                ldsm4(Af[mb], sA + off);
            }
            uint32_t Bh[4][2], Bl[4][2];
#pragma unroll
            for (int nb2 = 0; nb2 < 2; nb2++) {
                const uint32_t off = ((bRowL + nb2 * 16) * LDSS + bKL + ks) * 2;
                uint32_t rg[4];
                ldsm4(rg, sBh + off);
                Bh[nb2 * 2][0] = rg[0]; Bh[nb2 * 2][1] = rg[1];
                Bh[nb2 * 2 + 1][0] = rg[2]; Bh[nb2 * 2 + 1][1] = rg[3];
                ldsm4(rg, sBl + off);
                Bl[nb2 * 2][0] = rg[0]; Bl[nb2 * 2][1] = rg[1];
                Bl[nb2 * 2 + 1][0] = rg[2]; Bl[nb2 * 2 + 1][1] = rg[3];
            }
#pragma unroll
            for (int mb = 0; mb < 4; mb++)
#pragma unroll
                for (int nb = 0; nb < 4; nb++) {
                    mma16816h(acc[mb][nb], Af[mb], Bh[nb]);
                    mma16816h(acc[mb][nb], Af[mb], Bl[nb]);
                }
        }
        __syncthreads();
    }

#pragma unroll
    for (int mb = 0; mb < 4; mb++) {
        const int r = mBase + wm * 64 + mb * 16 + (lane >> 2);
#pragma unroll
        for (int nb = 0; nb < 4; nb++) {
            const int cc = nBase + wn * 32 + nb * 8 + (lane & 3) * 2;
            float v0 = acc[mb][nb][0], v1 = acc[mb][nb][1];
            float v2 = acc[mb][nb][2], v3 = acc[mb][nb][3];
            if (EPI == 0) {
                *(float2*)&C[(long)r * ldcL + cc] = make_float2(v0, v1);
                *(float2*)&C[(long)(r + 8) * ldcL + cc] = make_float2(v2, v3);
            } else {
                __half2 a = __halves2half2(__float2half_rn(v0), __float2half_rn(v1));
                __half2 b = __halves2half2(__float2half_rn(v2), __float2half_rn(v3));
                *(__half2*)&OL[(long)r * ldcL + cc] = a;
                *(__half2*)&OL[(long)(r + 8) * ldcL + cc] = b;
            }
        }
    }
}

// ---------------- fused K-up + V-up GEMM (homogeneous, 1024 CTAs) -------------
// bid < 512 : K[h] = C @ kupT[h]^T, hi/lo planes row-major [h][row][d]
// else      : V[h] = C @ vupT[h]^T, hi/lo planes TRANSPOSED [h][d][row]
__global__ __launch_bounds__(256, 2)
void gemm_kv(const __half* __restrict__ Cb,
             const __half* __restrict__ kuH, const __half* __restrict__ kuL,
             __half* __restrict__ kH, __half* __restrict__ kL,
             const __half* __restrict__ vuH, const __half* __restrict__ vuL,
             __half* __restrict__ vtH, __half* __restrict__ vtL)
{
    extern __shared__ __half smem[];
    const int tid = threadIdx.x;
    const int bid = blockIdx.x;
    const bool isV = bid >= 512;
    const int t = bid & 511;
    const int h = t >> 5;
    const int mBase = (t & 31) * 128;

    const __half* Bhi = (isV ? vuH : kuH) + (long)h * 128 * 512;
    const __half* Blo = (isV ? vuL : kuL) + (long)h * 128 * 512;
    __half* Ohi = isV ? (vtH + (long)h * 128 * 4096) : (kH + (long)h * 4096 * 128);
    __half* Olo = isV ? (vtL + (long)h * 128 * 4096) : (kL + (long)h * 4096 * 128);
    const int ldc = isV ? 4096 : 128;

    const int ldRow = tid >> 1;
    const int ldCol = (tid & 1) * 16;
    const uint32_t stsB = (uint32_t)(ldRow * LDSS + ldCol) * 2;

    const int lane = tid & 31;
    const int wid = tid >> 5;
    const int wm = wid >> 2;
    const int wn = wid & 3;
    const int aRowL = wm * 64 + (lane & 15);
    const int aKL = ((lane >> 4) << 3);
    const int bRowL = wn * 32 + ((lane >> 4) << 3) + (lane & 7);
    const int bKL = ((lane >> 3) & 1) << 3;

    const uint32_t smemBase = su(smem);
    const int nt = 512 / BK;

    const __half* pA  = Cb + (long)(mBase + ldRow) * 512 + ldCol;
    const __half* pBh = Bhi + (long)ldRow * 512 + ldCol;
    const __half* pBl = Blo + (long)ldRow * 512 + ldCol;

    auto loadStage = [&](int s, int kt) {
        const uint32_t d = smemBase + s * STAGE_BYTES + stsB;
        const long off = (long)kt * BK;
        cpa16(d, pA + off); cpa16(d + 16, pA + off + 8);
        cpa16(d + PLANE_BYTES, pBh + off); cpa16(d + PLANE_BYTES + 16, pBh + off + 8);
        cpa16(d + 2 * PLANE_BYTES, pBl + off); cpa16(d + 2 * PLANE_BYTES + 16, pBl + off + 8);
    };

    float acc[4][4][4];
#pragma unroll
    for (int i = 0; i < 4; i++)
#pragma unroll
        for (int j = 0; j < 4; j++)
#pragma unroll
            for (int k = 0; k < 4; k++) acc[i][j][k] = 0.f;

    loadStage(0, 0);
    asm volatile("cp.async.commit_group;" ::: "memory");

    for (int kt = 0; kt < nt; kt++) {
        asm volatile("cp.async.wait_group 0;" ::: "memory");
        __syncthreads();

        if (kt + 1 < nt) {
            loadStage((kt + 1) & 1, kt + 1);
            asm volatile("cp.async.commit_group;" ::: "memory");
        }

        const uint32_t sA  = smemBase + (kt & 1) * STAGE_BYTES;
        const uint32_t sBh = sA + PLANE_BYTES;
        const uint32_t sBl = sA + 2 * PLANE_BYTES;

#pragma unroll
        for (int ks = 0; ks < BK; ks += 16) {
            uint32_t Af[4][4];
#pragma unroll
            for (int mb = 0; mb < 4; mb++) {
                const uint32_t off = ((aRowL + mb * 16) * LDSS + aKL + ks) * 2;
                ldsm4(Af[mb], sA + off);
            }
            uint32_t Bh[4][2], Bl[4][2];
#pragma unroll
            for (int nb2 = 0; nb2 < 2; nb2++) {
                const uint32_t off = ((bRowL + nb2 * 16) * LDSS + bKL + ks) * 2;
                uint32_t rg[4];
                ldsm4(rg, sBh + off);
                Bh[nb2 * 2][0] = rg[0]; Bh[nb2 * 2][1] = rg[1];
                Bh[nb2 * 2 + 1][0] = rg[2]; Bh[nb2 * 2 + 1][1] = rg[3];
                ldsm4(rg, sBl + off);
                Bl[nb2 * 2][0] = rg[0]; Bl[nb2 * 2][1] = rg[1];
                Bl[nb2 * 2 + 1][0] = rg[2]; Bl[nb2 * 2 + 1][1] = rg[3];
            }
#pragma unroll
            for (int mb = 0; mb < 4; mb++)
#pragma unroll
                for (int nb = 0; nb < 4; nb++) {
                    mma16816h(acc[mb][nb], Af[mb], Bh[nb]);
                    mma16816h(acc[mb][nb], Af[mb], Bl[nb]);
                }
        }
        __syncthreads();
    }

#pragma unroll
    for (int mb = 0; mb < 4; mb++) {
        const int r = mBase + wm * 64 + mb * 16 + (lane >> 2);
#pragma unroll
        for (int nb = 0; nb < 4; nb++) {
            const int cc = wn * 32 + nb * 8 + (lane & 3) * 2;
            float v0 = acc[mb][nb][0], v1 = acc[mb][nb][1];
            float v2 = acc[mb][nb][2], v3 = acc[mb][nb][3];
            __half h0 = __float2half_rn(v0), h1 = __float2half_rn(v1);
            __half h2 = __float2half_rn(v2), h3 = __float2half_rn(v3);
            __half l0 = __float2half_rn(v0 - __half2float(h0));
            __half l1 = __float2half_rn(v1 - __half2float(h1));
            __half l2 = __float2half_rn(v2 - __half2float(h2));
            __half l3 = __float2half_rn(v3 - __half2float(h3));
            if (!isV) {
                *(__half2*)&Ohi[(long)r * ldc + cc] = __halves2half2(h0, h1);
                *(__half2*)&Ohi[(long)(r + 8) * ldc + cc] = __halves2half2(h2, h3);
                *(__half2*)&Olo[(long)r * ldc + cc] = __halves2half2(l0, l1);
                *(__half2*)&Olo[(long)(r + 8) * ldc + cc] = __halves2half2(l2, l3);
            } else {
                Ohi[(long)cc * ldc + r] = h0;
                Ohi[(long)(cc + 1) * ldc + r] = h1;
                Ohi[(long)cc * ldc + r + 8] = h2;
                Ohi[(long)(cc + 1) * ldc + r + 8] = h3;
                Olo[(long)cc * ldc + r] = l0;
                Olo[(long)(cc + 1) * ldc + r] = l1;
                Olo[(long)cc * ldc + r + 8] = l2;
                Olo[(long)(cc + 1) * ldc + r + 8] = l3;
            }
        }
    }
}

// ---------------- fp16 2-term flash attention ---------------------------------
// Q single plane; K,V hi/lo planes. S = Qh(Kh+Kl); O += Ph(Vh+Vl).
#define FQ_S 136
#define FV_S 72
#define FQ_O 0
#define FK_O 17408             // + stage*17408 ; hi +0, lo +8704
#define FV_O 52224             // + stage*18432 ; hi +0, lo +9216
#define FLASH_SMEM ((52224 + 2 * 18432) * 2)   // 178176 bytes
#define SCALE_F 0.08838834764831845f

__global__ __launch_bounds__(256)
void flash_tc(const __half* __restrict__ Q,
              const __half* __restrict__ Kh, const __half* __restrict__ Kl,
              const __half* __restrict__ Vth, const __half* __restrict__ Vtl,
              __half* __restrict__ AO)
{
    extern __shared__ __half fsm[];
    // LPT: heavy q-tiles first
    const int qt = (int)gridDim.x - 1 - (int)blockIdx.x;
    const int h = blockIdx.y, b = blockIdx.z;
    const int tid = threadIdx.x, lane = tid & 31, w = tid >> 5;
    const float slope = exp2f(-0.5f * (float)(h + 1));
    const int nt = 2 * qt + 2;

    const uint32_t fb = su(fsm);

    {
        const int r = tid >> 1, cb = (tid & 1) * 64;
        const __half* sq = Q + (long)(b * 2048 + qt * 128 + r) * 2048 + h * 128 + cb;
        const uint32_t dq = fb + (FQ_O + r * FQ_S + cb) * 2;
#pragma unroll
        for (int u = 0; u < 8; u++) cpa16(dq + u * 16, sq + u * 8);
    }
    auto loadKV = [&](int stg, int jt) {
        const int kr = tid >> 2, kcb = (tid & 3) * 32;
        const long krow = (long)h * 4096 + b * 2048 + jt * 64 + kr;
        const __half* skh = Kh + krow * 128 + kcb;
        const __half* skl = Kl + krow * 128 + kcb;
        const uint32_t kdh = fb + (FK_O + stg * 17408 + kr * FQ_S + kcb) * 2;
        const uint32_t kdl = kdh + 8704 * 2;
#pragma unroll
        for (int u = 0; u < 4; u++) { cpa16(kdh + u * 16, skh + u * 8); cpa16(kdl + u * 16, skl + u * 8); }
        const int vr = tid >> 1, vcb = (tid & 1) * 32;
        const long vrow = (long)h * 128 + vr;
        const __half* svh = Vth + vrow * 4096 + b * 2048 + jt * 64 + vcb;
        const __half* svl = Vtl + vrow * 4096 + b * 2048 + jt * 64 + vcb;
        const uint32_t vdh = fb + (FV_O + stg * 18432 + vr * FV_S + vcb) * 2;
        const uint32_t vdl = vdh + 9216 * 2;
#pragma unroll
        for (int u = 0; u < 4; u++) { cpa16(vdh + u * 16, svh + u * 8); cpa16(vdl + u * 16, svl + u * 8); }
    };
    loadKV(0, 0);
    asm volatile("cp.async.commit_group;");

    const int aRow = w * 16 + (lane & 15);
    const int aCol8 = (lane >> 4) << 3;
    const int bRow8 = ((lane >> 4) << 3) + (lane & 7);
    const int bCol8 = ((lane >> 3) & 1) << 3;

    float m0 = -1e30f, m1 = -1e30f, l0 = 0.f, l1 = 0.f;
    float o[16][4];
#pragma unroll
    for (int i = 0; i < 16; i++)
#pragma unroll
        for (int j = 0; j < 4; j++) o[i][j] = 0.f;

    const int grow0 = qt * 128 + w * 16 + (lane >> 2);

    for (int jt = 0; jt < nt; jt++) {
        const int cur = jt & 1;
        if (jt > 0) __syncthreads();
        if (jt + 1 < nt) {
            loadKV(cur ^ 1, jt + 1);
            asm volatile("cp.async.commit_group;");
            asm volatile("cp.async.wait_group 1;");
        } else {
            asm volatile("cp.async.wait_group 0;");
        }
        __syncthreads();

        const uint32_t bKH = fb + (FK_O + cur * 17408) * 2;
        const uint32_t bKL = bKH + 8704 * 2;
        const uint32_t bVH = fb + (FV_O + cur * 18432) * 2;
        const uint32_t bVL = bVH + 9216 * 2;

        float s[8][4];
#pragma unroll
        for (int i = 0; i < 8; i++)
#pragma unroll
            for (int j = 0; j < 4; j++) s[i][j] = 0.f;

#pragma unroll
        for (int ks = 0; ks < 8; ks++) {
            uint32_t qf[4];
            const uint32_t aoff = (uint32_t)(aRow * FQ_S + ks * 16 + aCol8) * 2;
            ldsm4(qf, fb + FQ_O * 2 + aoff);
#pragma unroll
            for (int nb2 = 0; nb2 < 4; nb2++) {
                const uint32_t boff = (uint32_t)((nb2 * 16 + bRow8) * FQ_S + ks * 16 + bCol8) * 2;
                uint32_t kh[4], kl[4];
                ldsm4(kh, bKH + boff);
                ldsm4(kl, bKL + boff);
                mma16816h(s[2 * nb2],     qf, &kh[0]);
                mma16816h(s[2 * nb2],     qf, &kl[0]);
                mma16816h(s[2 * nb2 + 1], qf, &kh[2]);
                mma16816h(s[2 * nb2 + 1], qf, &kl[2]);
            }
        }

#pragma unroll
        for (int nb = 0; nb < 8; nb++) {
#pragma unroll
            for (int j = 0; j < 2; j++) {
                const int gc = jt * 64 + nb * 8 + (lane & 3) * 2 + j;
                float v = s[nb][j];
                s[nb][j] = (gc > grow0) ? -1e30f
                          : v * SCALE_F - slope * (float)(grow0 - gc);
                float v2 = s[nb][2 + j];
                s[nb][2 + j] = (gc > grow0 + 8) ? -1e30f
                          : v2 * SCALE_F - slope * (float)(grow0 + 8 - gc);
            }
        }

        float mx0 = -1e30f, mx1 = -1e30f;
#pragma unroll
        for (int nb = 0; nb < 8; nb++) {
            mx0 = fmaxf(mx0, fmaxf(s[nb][0], s[nb][1]));
            mx1 = fmaxf(mx1, fmaxf(s[nb][2], s[nb][3]));
        }
        mx0 = fmaxf(mx0, __shfl_xor_sync(0xffffffffu, mx0, 1));
        mx0 = fmaxf(mx0, __shfl_xor_sync(0xffffffffu, mx0, 2));
        mx1 = fmaxf(mx1, __shfl_xor_sync(0xffffffffu, mx1, 1));
        mx1 = fmaxf(mx1, __shfl_xor_sync(0xffffffffu, mx1, 2));
        const float mn0 = fmaxf(m0, mx0), mn1 = fmaxf(m1, mx1);
        const float al0 = __expf(m0 - mn0), al1 = __expf(m1 - mn1);
        m0 = mn0; m1 = mn1;

        // exp -> round to fp16 (P used in MMA); accumulate l from the ROUNDED p
        float sum0 = 0.f, sum1 = 0.f;
#pragma unroll
        for (int nb = 0; nb < 8; nb++) {
            s[nb][0] = __half2float(__float2half_rn(__expf(s[nb][0] - mn0))); sum0 += s[nb][0];
            s[nb][1] = __half2float(__float2half_rn(__expf(s[nb][1] - mn0))); sum0 += s[nb][1];
            s[nb][2] = __half2float(__float2half_rn(__expf(s[nb][2] - mn1))); sum1 += s[nb][2];
            s[nb][3] = __half2float(__float2half_rn(__expf(s[nb][3] - mn1))); sum1 += s[nb][3];
        }
        sum0 += __shfl_xor_sync(0xffffffffu, sum0, 1);
        sum0 += __shfl_xor_sync(0xffffffffu, sum0, 2);
        sum1 += __shfl_xor_sync(0xffffffffu, sum1, 1);
        sum1 += __shfl_xor_sync(0xffffffffu, sum1, 2);
        l0 = l0 * al0 + sum0;
        l1 = l1 * al1 + sum1;

#pragma unroll
        for (int nb = 0; nb < 16; nb++) {
            o[nb][0] *= al0; o[nb][1] *= al0;
            o[nb][2] *= al1; o[nb][3] *= al1;
        }

        uint32_t ph[4][4];
#pragma unroll
        for (int kb = 0; kb < 4; kb++) {
#pragma unroll
            for (int q = 0; q < 4; q++) {
                const float x = s[2 * kb + (q >> 1)][(q & 1) * 2 + 0];
                const float y = s[2 * kb + (q >> 1)][(q & 1) * 2 + 1];
                ph[kb][q] = pack2h(__float2half_rn(x), __float2half_rn(y));
            }
        }

#pragma unroll
        for (int kb = 0; kb < 4; kb++) {
#pragma unroll
            for (int nb2 = 0; nb2 < 8; nb2++) {
                const uint32_t voff = (uint32_t)((nb2 * 16 + bRow8) * FV_S + kb * 16 + bCol8) * 2;
                uint32_t vh[4], vl[4];
                ldsm4(vh, bVH + voff);
                ldsm4(vl, bVL + voff);
                mma16816h(o[2 * nb2],     ph[kb], &vh[0]);
                mma16816h(o[2 * nb2],     ph[kb], &vl[0]);
                mma16816h(o[2 * nb2 + 1], ph[kb], &vh[2]);
                mma16816h(o[2 * nb2 + 1], ph[kb], &vl[2]);
            }
        }
    }

    const float inv0 = 1.f / l0, inv1 = 1.f / l1;
    const long row0 = (long)b * 2048 + qt * 128 + w * 16 + (lane >> 2);
#pragma unroll
    for (int nb = 0; nb < 16; nb++) {
        const int c = h * 128 + nb * 8 + (lane & 3) * 2;
        *(__half2*)&AO[row0 * 2048 + c] =
            __halves2half2(__float2half_rn(o[nb][0] * inv0), __float2half_rn(o[nb][1] * inv0));
        *(__half2*)&AO[(row0 + 8) * 2048 + c] =
            __halves2half2(__float2half_rn(o[nb][2] * inv1), __float2half_rn(o[nb][3] * inv1));
    }
}

// ---------------- launch ------------------------------------------------------
extern "C" void kernel_launch(void* const* d_in, const int* in_sizes, int n_in,
                              void* d_out, int out_size)
{
    const float* X    = (const float*)d_in[0];
    const float* Wqd  = (const float*)d_in[1];
    const float* Wqu  = (const float*)d_in[2];
    const float* Wkvd = (const float*)d_in[3];
    const float* kup  = (const float*)d_in[4];
    const float* vup  = (const float*)d_in[5];
    const float* Wo   = (const float*)d_in[6];
    float* out = (float*)d_out;

    __half *x, *xq, *cb, *q, *kH, *kL, *vtH, *vtL, *ao;
    cudaGetSymbolAddress((void**)&x, g_X);
    cudaGetSymbolAddress((void**)&xq, g_Xq);
    cudaGetSymbolAddress((void**)&cb, g_Cb);
    cudaGetSymbolAddress((void**)&q, g_Q);
    cudaGetSymbolAddress((void**)&kH, g_Kh);   cudaGetSymbolAddress((void**)&kL, g_Kl);
    cudaGetSymbolAddress((void**)&vtH, g_Vth); cudaGetSymbolAddress((void**)&vtL, g_Vtl);
    cudaGetSymbolAddress((void**)&ao, g_AO);

    __half *wqdH, *wqdL, *wquH, *wquL, *wkvH, *wkvL, *woH, *woL;
    __half *kuH, *kuL, *vuH, *vuL;
    cudaGetSymbolAddress((void**)&wqdH, g_Wqd_hi); cudaGetSymbolAddress((void**)&wqdL, g_Wqd_lo);
    cudaGetSymbolAddress((void**)&wquH, g_Wqu_hi); cudaGetSymbolAddress((void**)&wquL, g_Wqu_lo);
    cudaGetSymbolAddress((void**)&wkvH, g_Wkvd_hi); cudaGetSymbolAddress((void**)&wkvL, g_Wkvd_lo);
    cudaGetSymbolAddress((void**)&woH, g_Wo_hi); cudaGetSymbolAddress((void**)&woL, g_Wo_lo);
    cudaGetSymbolAddress((void**)&kuH, g_kupT_hi); cudaGetSymbolAddress((void**)&kuL, g_kupT_lo);
    cudaGetSymbolAddress((void**)&vuH, g_vupT_hi); cudaGetSymbolAddress((void**)&vuL, g_vupT_lo);

    cudaFuncSetAttribute(gemm_tc<0>, cudaFuncAttributeMaxDynamicSharedMemorySize, GEMM_SMEM);
    cudaFuncSetAttribute(gemm_tc<1>, cudaFuncAttributeMaxDynamicSharedMemorySize, GEMM_SMEM);
    cudaFuncSetAttribute(gemm_kv, cudaFuncAttributeMaxDynamicSharedMemorySize, GEMM_SMEM);
    cudaFuncSetAttribute(flash_tc, cudaFuncAttributeMaxDynamicSharedMemorySize, FLASH_SMEM);

    // ---- prep ----
    conv_single4<<<(4096 * 2048 / 4 + 255) / 256, 256>>>(X, x, 4096 * 2048 / 4);
    conv_pair4<<<(1536 * 2048 / 4 + 255) / 256, 256>>>(Wqd, wqdH, wqdL, 1536 * 2048 / 4);
    conv_pair4<<<(2048 * 1536 / 4 + 255) / 256, 256>>>(Wqu, wquH, wquL, 2048 * 1536 / 4);
    conv_pair4<<<(512 * 2048 / 4 + 255) / 256, 256>>>(Wkvd, wkvH, wkvL, 512 * 2048 / 4);
    conv_pair4<<<(2048 * 2048 / 4 + 255) / 256, 256>>>(Wo, woH, woL, 2048 * 2048 / 4);
    conv_transpose<<<(16 * 512 * 128 + 255) / 256, 256>>>(kup, kuH, kuL, 16, 512, 128);
    conv_transpose<<<(16 * 512 * 128 + 255) / 256, 256>>>(vup, vuH, vuL, 16, 512, 128);

    // 1) [Xq | C] = X @ [Wqd | Wkvd]^T  (merged-N, fp16 single outs)
    gemm_tc<1><<<dim3(16, 32), 256, GEMM_SMEM>>>(x, wqdH, wqdL, nullptr, xq,
        4096, 2048, 2048, 2048, 1536,
        wkvH, wkvL, cb, 1536, 512);
    // 2) Q = Xq @ Wq_up^T
    gemm_tc<1><<<dim3(16, 32), 256, GEMM_SMEM>>>(xq, wquH, wquL, nullptr, q,
        4096, 2048, 1536, 1536, 2048,
        nullptr, nullptr, nullptr, 1 << 30, 0);
    // 3) fused K/V up-projections (hi/lo outs for the flash B-side)
    gemm_kv<<<1024, 256, GEMM_SMEM>>>(cb, kuH, kuL, kH, kL, vuH, vuL, vtH, vtL);
    // 4) attention (LPT)
    flash_tc<<<dim3(16, 16, 2), 256, FLASH_SMEM>>>(q, kH, kL, vtH, vtL, ao);
    // 5) out = AO @ Wo^T (fp32)
    gemm_tc<0><<<dim3(16, 32), 256, GEMM_SMEM>>>(ao, woH, woL, out, nullptr,
        4096, 2048, 2048, 2048, 2048,
        nullptr, nullptr, nullptr, 1 << 30, 0);
}